// round 1
// baseline (speedup 1.0000x reference)
#include <cuda_runtime.h>

// TriangleMultiplicativeUpdate, fused single-pass fp32 kernel using
// fma.rn.f32x2 (packed fp32 FMA, 2x FFMA rate on Blackwell).
//
// Math (per row r of M=B*N*N, C=128):
//   zn  = LN(z_r) * ln_in_w + ln_in_b
//   a   = (zn@w_ap^T + b_ap) * sigmoid(zn@w_ag^T + b_ag) * mask_r
//   b   = (zn@w_bp^T + b_bp) * sigmoid(zn@w_bg^T + b_bg) * mask_r
//   x   = a * b                      (the einsum is elementwise!)
//   xn  = LN(x) * ln_out_w + ln_out_b
//   out = (xn@w_z^T + b_z) * sigmoid(zn@w_g^T + b_g)

#define CC 128            // channels
#define RT 128            // rows per CTA tile
#define ZS 130            // znT row stride (pad, even for 8B-aligned pairs)
#define BS 132            // buf row stride (pad, 16B-aligned, de-conflicts LN reads)
#define NTHREADS 512

// Pre-transposed weights: g_wt[slot][k*CC + c] = W[c][k]
// slots: 0=w_ap 1=w_ag 2=w_bp 3=w_bg 4=w_g 5=w_z
__device__ __align__(16) float g_wt[6][CC * CC];

// ---------------- packed fp32x2 helpers ----------------
__device__ __forceinline__ void ffma2(unsigned long long &d,
                                      unsigned long long a,
                                      unsigned long long b) {
    asm("fma.rn.f32x2 %0, %1, %2, %0;" : "+l"(d) : "l"(a), "l"(b));
}
__device__ __forceinline__ unsigned long long dup2(float x) {
    unsigned long long u;
    asm("mov.b64 %0, {%1, %2};" : "=l"(u) : "f"(x), "f"(x));
    return u;
}
__device__ __forceinline__ float2 unpack2(unsigned long long u) {
    float2 r;
    asm("mov.b64 {%0, %1}, %2;" : "=f"(r.x), "=f"(r.y) : "l"(u));
    return r;
}
__device__ __forceinline__ float sigm(float x) {
    return 1.0f / (1.0f + __expf(-x));
}

// ---------------- 128-row x 128-col x 128-k tile matmul ----------------
// S: znT-layout shared [k][row] (stride ZS). W: shared [k][col] (stride CC).
// Each warp owns 8 rows (rowbase), each lane 4 cols (lane*4).
// acc[p*4+c]: packed pair = rows (rowbase+2p, rowbase+2p+1), col lane*4+c.
__device__ __forceinline__ void mm128(const float* S, const float* W,
                                      int rowbase, int lane,
                                      unsigned long long acc[16]) {
#pragma unroll
    for (int i = 0; i < 16; i++) acc[i] = 0ull;
#pragma unroll 4
    for (int k = 0; k < CC; k++) {
        const float* sr = S + k * ZS + rowbase;
        unsigned long long z0 = *(const unsigned long long*)(sr + 0);
        unsigned long long z1 = *(const unsigned long long*)(sr + 2);
        unsigned long long z2 = *(const unsigned long long*)(sr + 4);
        unsigned long long z3 = *(const unsigned long long*)(sr + 6);
        float4 wv = *(const float4*)(W + k * CC + lane * 4);
        unsigned long long w0 = dup2(wv.x), w1 = dup2(wv.y);
        unsigned long long w2 = dup2(wv.z), w3 = dup2(wv.w);
        ffma2(acc[0],  z0, w0); ffma2(acc[1],  z0, w1);
        ffma2(acc[2],  z0, w2); ffma2(acc[3],  z0, w3);
        ffma2(acc[4],  z1, w0); ffma2(acc[5],  z1, w1);
        ffma2(acc[6],  z1, w2); ffma2(acc[7],  z1, w3);
        ffma2(acc[8],  z2, w0); ffma2(acc[9],  z2, w1);
        ffma2(acc[10], z2, w2); ffma2(acc[11], z2, w3);
        ffma2(acc[12], z3, w0); ffma2(acc[13], z3, w1);
        ffma2(acc[14], z3, w2); ffma2(acc[15], z3, w3);
    }
}

// Copy one pre-transposed 128x128 weight matrix into shared memory.
__device__ __forceinline__ void load_wt(float* wt, int slot, int t) {
    const float4* src = (const float4*)(g_wt[slot]);
    float4* dst = (float4*)wt;
#pragma unroll
    for (int i = 0; i < 8; i++)
        dst[t + i * NTHREADS] = __ldg(src + t + i * NTHREADS);
}

// ---------------- weight transpose prep kernel ----------------
__global__ void kTranspose(const float* __restrict__ w0, const float* __restrict__ w1,
                           const float* __restrict__ w2, const float* __restrict__ w3,
                           const float* __restrict__ w4, const float* __restrict__ w5) {
    __shared__ float tile[32][33];
    const float* w;
    switch (blockIdx.z) {
        case 0: w = w0; break; case 1: w = w1; break; case 2: w = w2; break;
        case 3: w = w3; break; case 4: w = w4; break; default: w = w5; break;
    }
    float* dst = g_wt[blockIdx.z];
    int bx = blockIdx.x * 32, by = blockIdx.y * 32;
    int tx = threadIdx.x, ty = threadIdx.y;
#pragma unroll
    for (int j = 0; j < 32; j += 8)
        tile[ty + j][tx] = w[(by + ty + j) * CC + bx + tx];
    __syncthreads();
#pragma unroll
    for (int j = 0; j < 32; j += 8)
        dst[(bx + ty + j) * CC + by + tx] = tile[tx][ty + j];
}

// ---------------- main fused kernel ----------------
__global__ void __launch_bounds__(NTHREADS, 1)
tmu_kernel(const float* __restrict__ z, const float* __restrict__ mask,
           const float* __restrict__ b_ap, const float* __restrict__ b_ag,
           const float* __restrict__ b_bp, const float* __restrict__ b_bg,
           const float* __restrict__ b_g,  const float* __restrict__ b_z,
           const float* __restrict__ ln_in_w,  const float* __restrict__ ln_in_b,
           const float* __restrict__ ln_out_w, const float* __restrict__ ln_out_b,
           float* __restrict__ out) {
    extern __shared__ float sm[];
    float* znT = sm;                 // [CC][ZS]   transposed zn / xn
    float* wt  = znT + CC * ZS;      // [CC][CC]   current weight (k-major)
    float* buf = wt + CC * CC;       // [RT][BS]   a, then x
    float* mk  = buf + RT * BS;      // [RT]       mask per row

    const int t = threadIdx.x;
    const int lane = t & 31;
    const int warp = t >> 5;
    const int rowbase = warp << 3;              // 16 warps * 8 rows = 128
    const size_t row0 = (size_t)blockIdx.x * RT;

    // ---- T1: load z tile, LayerNorm_in, store transposed ----
    {
        const int r = t >> 2, q = t & 3;        // 4 threads per row
        const float* zr = z + (row0 + r) * CC + q * 32;
        float v[32];
        float s = 0.f, s2 = 0.f;
#pragma unroll
        for (int i = 0; i < 8; i++) {
            float4 f = __ldg((const float4*)(zr + 4 * i));
            v[4*i] = f.x; v[4*i+1] = f.y; v[4*i+2] = f.z; v[4*i+3] = f.w;
            s  += f.x + f.y + f.z + f.w;
            s2 += f.x*f.x + f.y*f.y + f.z*f.z + f.w*f.w;
        }
        s  += __shfl_xor_sync(0xffffffffu, s, 1);
        s  += __shfl_xor_sync(0xffffffffu, s, 2);
        s2 += __shfl_xor_sync(0xffffffffu, s2, 1);
        s2 += __shfl_xor_sync(0xffffffffu, s2, 2);
        float mu = s * (1.f / CC);
        float rstd = rsqrtf(fmaxf(s2 * (1.f / CC) - mu * mu, 0.f) + 1e-5f);
#pragma unroll
        for (int i = 0; i < 32; i++) {
            int c = q * 32 + i;
            znT[c * ZS + r] = (v[i] - mu) * rstd * __ldg(ln_in_w + c) + __ldg(ln_in_b + c);
        }
        if (q == 0) mk[r] = __ldg(mask + row0 + r);
    }
    __syncthreads();

    unsigned long long accP[16], accG[16];

    // ---- a = (zn@w_ap^T + b_ap) * sigmoid(zn@w_ag^T + b_ag) * mask ----
    load_wt(wt, 0, t); __syncthreads();
    mm128(znT, wt, rowbase, lane, accP);
    __syncthreads();
    load_wt(wt, 1, t); __syncthreads();
    mm128(znT, wt, rowbase, lane, accG);
    {
        float4 bp4 = __ldg((const float4*)(b_ap + lane * 4));
        float4 bg4 = __ldg((const float4*)(b_ag + lane * 4));
        float bp[4] = {bp4.x, bp4.y, bp4.z, bp4.w};
        float bg[4] = {bg4.x, bg4.y, bg4.z, bg4.w};
#pragma unroll
        for (int p = 0; p < 4; p++) {
            int r0 = rowbase + 2 * p;
            float m0 = mk[r0], m1 = mk[r0 + 1];
            float o0[4], o1[4];
#pragma unroll
            for (int c = 0; c < 4; c++) {
                float2 P = unpack2(accP[p * 4 + c]);
                float2 G = unpack2(accG[p * 4 + c]);
                o0[c] = (P.x + bp[c]) * sigm(G.x + bg[c]) * m0;
                o1[c] = (P.y + bp[c]) * sigm(G.y + bg[c]) * m1;
            }
            *(float4*)(buf + r0 * BS + lane * 4)       = make_float4(o0[0], o0[1], o0[2], o0[3]);
            *(float4*)(buf + (r0 + 1) * BS + lane * 4) = make_float4(o1[0], o1[1], o1[2], o1[3]);
        }
    }
    __syncthreads();

    // ---- b, then x = a*b (in-place in buf) ----
    load_wt(wt, 2, t); __syncthreads();
    mm128(znT, wt, rowbase, lane, accP);
    __syncthreads();
    load_wt(wt, 3, t); __syncthreads();
    mm128(znT, wt, rowbase, lane, accG);
    {
        float4 bp4 = __ldg((const float4*)(b_bp + lane * 4));
        float4 bg4 = __ldg((const float4*)(b_bg + lane * 4));
        float bp[4] = {bp4.x, bp4.y, bp4.z, bp4.w};
        float bg[4] = {bg4.x, bg4.y, bg4.z, bg4.w};
#pragma unroll
        for (int p = 0; p < 4; p++) {
            int r0 = rowbase + 2 * p;
            float m0 = mk[r0], m1 = mk[r0 + 1];
            float4 av0 = *(const float4*)(buf + r0 * BS + lane * 4);
            float4 av1 = *(const float4*)(buf + (r0 + 1) * BS + lane * 4);
            float a0[4] = {av0.x, av0.y, av0.z, av0.w};
            float a1[4] = {av1.x, av1.y, av1.z, av1.w};
            float o0[4], o1[4];
#pragma unroll
            for (int c = 0; c < 4; c++) {
                float2 P = unpack2(accP[p * 4 + c]);
                float2 G = unpack2(accG[p * 4 + c]);
                o0[c] = a0[c] * ((P.x + bp[c]) * sigm(G.x + bg[c]) * m0);
                o1[c] = a1[c] * ((P.y + bp[c]) * sigm(G.y + bg[c]) * m1);
            }
            *(float4*)(buf + r0 * BS + lane * 4)       = make_float4(o0[0], o0[1], o0[2], o0[3]);
            *(float4*)(buf + (r0 + 1) * BS + lane * 4) = make_float4(o1[0], o1[1], o1[2], o1[3]);
        }
    }
    __syncthreads();

    // ---- gate = sigmoid(zn@w_g^T + b_g), held in registers ----
    load_wt(wt, 4, t); __syncthreads();
    mm128(znT, wt, rowbase, lane, accG);
    float gate[32];
    {
        float4 bg4 = __ldg((const float4*)(b_g + lane * 4));
        float bg[4] = {bg4.x, bg4.y, bg4.z, bg4.w};
#pragma unroll
        for (int i = 0; i < 16; i++) {
            float2 G = unpack2(accG[i]);
            int c = i & 3;
            gate[2 * i]     = sigm(G.x + bg[c]);
            gate[2 * i + 1] = sigm(G.y + bg[c]);
        }
    }
    __syncthreads();   // all reads of znT (w_g matmul) done everywhere

    // ---- T6: LayerNorm_out over x (buf), write transposed into znT ----
    {
        const int r = t >> 2, q = t & 3;
        const float* br = buf + r * BS + q * 32;
        float s = 0.f, s2 = 0.f;
#pragma unroll
        for (int i = 0; i < 8; i++) {
            float4 f = *(const float4*)(br + 4 * i);
            s  += f.x + f.y + f.z + f.w;
            s2 += f.x*f.x + f.y*f.y + f.z*f.z + f.w*f.w;
        }
        s  += __shfl_xor_sync(0xffffffffu, s, 1);
        s  += __shfl_xor_sync(0xffffffffu, s, 2);
        s2 += __shfl_xor_sync(0xffffffffu, s2, 1);
        s2 += __shfl_xor_sync(0xffffffffu, s2, 2);
        float mu = s * (1.f / CC);
        float rstd = rsqrtf(fmaxf(s2 * (1.f / CC) - mu * mu, 0.f) + 1e-5f);
#pragma unroll
        for (int i = 0; i < 32; i++) {
            int c = q * 32 + i;
            znT[c * ZS + r] = (br[i] - mu) * rstd * __ldg(ln_out_w + c) + __ldg(ln_out_b + c);
        }
    }
    load_wt(wt, 5, t);
    __syncthreads();

    // ---- out = (xn @ w_z^T + b_z) * gate ----
    mm128(znT, wt, rowbase, lane, accP);
    {
        float4 bz4 = __ldg((const float4*)(b_z + lane * 4));
        float bz[4] = {bz4.x, bz4.y, bz4.z, bz4.w};
#pragma unroll
        for (int p = 0; p < 4; p++) {
            int r0 = rowbase + 2 * p;
            float o0[4], o1[4];
#pragma unroll
            for (int c = 0; c < 4; c++) {
                float2 O = unpack2(accP[p * 4 + c]);
                o0[c] = (O.x + bz[c]) * gate[2 * (p * 4 + c)];
                o1[c] = (O.y + bz[c]) * gate[2 * (p * 4 + c) + 1];
            }
            *(float4*)(out + (row0 + r0) * CC + lane * 4)     = make_float4(o0[0], o0[1], o0[2], o0[3]);
            *(float4*)(out + (row0 + r0 + 1) * CC + lane * 4) = make_float4(o1[0], o1[1], o1[2], o1[3]);
        }
    }
}

extern "C" void kernel_launch(void* const* d_in, const int* in_sizes, int n_in,
                              void* d_out, int out_size) {
    const float* z        = (const float*)d_in[0];
    const float* mask     = (const float*)d_in[1];
    const float* w_ap     = (const float*)d_in[2];
    const float* b_ap     = (const float*)d_in[3];
    const float* w_bp     = (const float*)d_in[4];
    const float* b_bp     = (const float*)d_in[5];
    const float* w_ag     = (const float*)d_in[6];
    const float* b_ag     = (const float*)d_in[7];
    const float* w_bg     = (const float*)d_in[8];
    const float* b_bg     = (const float*)d_in[9];
    const float* w_g      = (const float*)d_in[10];
    const float* b_g      = (const float*)d_in[11];
    const float* w_z      = (const float*)d_in[12];
    const float* b_z      = (const float*)d_in[13];
    const float* ln_in_w  = (const float*)d_in[14];
    const float* ln_in_b  = (const float*)d_in[15];
    const float* ln_out_w = (const float*)d_in[16];
    const float* ln_out_b = (const float*)d_in[17];
    float* out = (float*)d_out;

    const int rows = in_sizes[1];        // mask elements = B*N*N
    const int nblocks = rows / RT;       // 147456 / 128 = 1152

    const int smem = (CC * ZS + CC * CC + RT * BS + RT) * (int)sizeof(float);
    cudaFuncSetAttribute(tmu_kernel, cudaFuncAttributeMaxDynamicSharedMemorySize, smem);

    // prep: transpose the 6 weight matrices into k-major scratch
    kTranspose<<<dim3(4, 4, 6), dim3(32, 8)>>>(w_ap, w_ag, w_bp, w_bg, w_g, w_z);

    tmu_kernel<<<nblocks, NTHREADS, smem>>>(z, mask,
                                            b_ap, b_ag, b_bp, b_bg, b_g, b_z,
                                            ln_in_w, ln_in_b, ln_out_w, ln_out_b,
                                            out);
}

// round 3
// speedup vs baseline: 2.0186x; 2.0186x over previous
#include <cuda_runtime.h>
#include <cuda_bf16.h>
#include <stdint.h>

// TriangleMultiplicativeUpdate, fully fused, warp-level tensor cores
// (mma.sync.m16n8k16 bf16 — baseline PTX, works under compute_100 lowering).
// Per 128-row tile: zn=LN_in(z); 6 matmuls vs 128x128 weights with a 3-term
// bf16 hi/lo split (Ah*Bh + Ah*Bl + Al*Bh, fp32 accum) ~1e-6 accuracy;
// x=a*b elementwise; xn=LN_out(x); out=(xn@w_z^T+b_z)*sigmoid(zn@w_g^T+b_g).

#define NT 512
#define STR 272u   // smem row stride in bytes (136 bf16): conflict-free ldmatrix

#define OFF_ZH  0u
#define OFF_ZL  34816u
#define OFF_W0H 69632u
#define OFF_W0L 104448u
#define OFF_W1H 139264u
#define OFF_W1L 174080u
#define OFF_SB  208896u   // 8 x 128 floats (biases, ln_out w/b)
#define OFF_MK  212992u   // 128 floats (mask)
#define OFF_RED 213504u   // 128 x 4 float2 (LN_out partials)
#define SMEM_BYTES 217600

// weights as bf16 hi/lo, linear [n][k] (inputs are already [c_out][k])
__device__ __align__(16) __nv_bfloat16 g_w[6][2][128 * 128];

__device__ __forceinline__ uint32_t s2u(const void* p) {
    uint32_t a;
    asm("{ .reg .u64 t; cvta.to.shared.u64 t, %1; cvt.u32.u64 %0, t; }" : "=r"(a) : "l"(p));
    return a;
}

#define LDSM4(r, a) \
    asm volatile("ldmatrix.sync.aligned.m8n8.x4.shared.b16 {%0,%1,%2,%3}, [%4];" \
        : "=r"((r)[0]), "=r"((r)[1]), "=r"((r)[2]), "=r"((r)[3]) : "r"(a))

#define MMAOP(d, a, b0, b1) \
    asm volatile("mma.sync.aligned.m16n8k16.row.col.f32.bf16.bf16.f32 " \
        "{%0,%1,%2,%3}, {%4,%5,%6,%7}, {%8,%9}, {%0,%1,%2,%3};" \
        : "+f"((d)[0]), "+f"((d)[1]), "+f"((d)[2]), "+f"((d)[3]) \
        : "r"((a)[0]), "r"((a)[1]), "r"((a)[2]), "r"((a)[3]), "r"(b0), "r"(b1))

#define CPA16(dst, src) \
    asm volatile("cp.async.cg.shared.global [%0], [%1], 16;" :: "r"(dst), "l"(src))
#define CP_COMMIT() asm volatile("cp.async.commit_group;" ::: "memory")
#define CP_WAIT0()  asm volatile("cp.async.wait_group 0;" ::: "memory")

__device__ __forceinline__ float sigm(float x) { return 1.0f / (1.0f + __expf(-x)); }

// 128x128x128 matmul with 3-term bf16 split; acc += zn @ W^T
__device__ __forceinline__ void mm(float* acc, uint32_t ah, uint32_t al,
                                   uint32_t bh, uint32_t bl,
                                   uint32_t ao0, uint32_t ao1,
                                   uint32_t bo0, uint32_t bo1) {
#pragma unroll 1
    for (int k = 0; k < 8; k++) {
        uint32_t ko = (uint32_t)k * 32u;
        uint32_t Ah0[4], Ah1[4], Al0[4], Al1[4];
        uint32_t Bh0[4], Bh1[4], Bl0[4], Bl1[4];
        LDSM4(Ah0, ah + ao0 + ko); LDSM4(Ah1, ah + ao1 + ko);
        LDSM4(Al0, al + ao0 + ko); LDSM4(Al1, al + ao1 + ko);
        LDSM4(Bh0, bh + bo0 + ko); LDSM4(Bh1, bh + bo1 + ko);
        LDSM4(Bl0, bl + bo0 + ko); LDSM4(Bl1, bl + bo1 + ko);
        // pass hh
        MMAOP(acc + 0,  Ah0, Bh0[0], Bh0[1]); MMAOP(acc + 4,  Ah0, Bh0[2], Bh0[3]);
        MMAOP(acc + 8,  Ah0, Bh1[0], Bh1[1]); MMAOP(acc + 12, Ah0, Bh1[2], Bh1[3]);
        MMAOP(acc + 16, Ah1, Bh0[0], Bh0[1]); MMAOP(acc + 20, Ah1, Bh0[2], Bh0[3]);
        MMAOP(acc + 24, Ah1, Bh1[0], Bh1[1]); MMAOP(acc + 28, Ah1, Bh1[2], Bh1[3]);
        // pass hl
        MMAOP(acc + 0,  Ah0, Bl0[0], Bl0[1]); MMAOP(acc + 4,  Ah0, Bl0[2], Bl0[3]);
        MMAOP(acc + 8,  Ah0, Bl1[0], Bl1[1]); MMAOP(acc + 12, Ah0, Bl1[2], Bl1[3]);
        MMAOP(acc + 16, Ah1, Bl0[0], Bl0[1]); MMAOP(acc + 20, Ah1, Bl0[2], Bl0[3]);
        MMAOP(acc + 24, Ah1, Bl1[0], Bl1[1]); MMAOP(acc + 28, Ah1, Bl1[2], Bl1[3]);
        // pass lh
        MMAOP(acc + 0,  Al0, Bh0[0], Bh0[1]); MMAOP(acc + 4,  Al0, Bh0[2], Bh0[3]);
        MMAOP(acc + 8,  Al0, Bh1[0], Bh1[1]); MMAOP(acc + 12, Al0, Bh1[2], Bh1[3]);
        MMAOP(acc + 16, Al1, Bh0[0], Bh0[1]); MMAOP(acc + 20, Al1, Bh0[2], Bh0[3]);
        MMAOP(acc + 24, Al1, Bh1[0], Bh1[1]); MMAOP(acc + 28, Al1, Bh1[2], Bh1[3]);
    }
}

// async-copy one weight (hi+lo, 64KB linear) into a padded smem slot
__device__ __forceinline__ void prefetch(uint32_t dstH, uint32_t dstL, int widx, int t) {
    const char* sh = (const char*)g_w[widx][0];
    const char* sl = (const char*)g_w[widx][1];
#pragma unroll
    for (int i = 0; i < 4; i++) {
        int cid = t + i * NT;                  // 2048 16B chunks per matrix
        uint32_t d = (uint32_t)(cid >> 4) * STR + (uint32_t)(cid & 15) * 16u;
        CPA16(dstH + d, sh + (size_t)cid * 16);
        CPA16(dstL + d, sl + (size_t)cid * 16);
    }
    CP_COMMIT();
}

__global__ void kPrep(const float* __restrict__ w0, const float* __restrict__ w1,
                      const float* __restrict__ w2, const float* __restrict__ w3,
                      const float* __restrict__ w4, const float* __restrict__ w5) {
    const float* w;
    switch (blockIdx.x) {
        case 0: w = w0; break; case 1: w = w1; break; case 2: w = w2; break;
        case 3: w = w3; break; case 4: w = w4; break; default: w = w5; break;
    }
    __nv_bfloat16* h = g_w[blockIdx.x][0];
    __nv_bfloat16* l = g_w[blockIdx.x][1];
    for (int i = threadIdx.x; i < 128 * 128; i += blockDim.x) {
        float v = __ldg(w + i);
        __nv_bfloat16 hh = __float2bfloat16(v);
        h[i] = hh;
        l[i] = __float2bfloat16(v - __bfloat162float(hh));
    }
}

__global__ void __launch_bounds__(NT, 1)
tmu_kernel(const float* __restrict__ z, const float* __restrict__ mask,
           const float* __restrict__ b_ap, const float* __restrict__ b_ag,
           const float* __restrict__ b_bp, const float* __restrict__ b_bg,
           const float* __restrict__ b_g,  const float* __restrict__ b_z,
           const float* __restrict__ ln_in_w,  const float* __restrict__ ln_in_b,
           const float* __restrict__ ln_out_w, const float* __restrict__ ln_out_b,
           float* __restrict__ out) {
    extern __shared__ char sm[];
    const uint32_t smb = s2u(sm);
    const int t = threadIdx.x;
    const int w = t >> 5, lid = t & 31;
    const int quad = lid >> 2, qt = lid & 3;
    const int wr = (w & 3) * 32, wc = (w >> 2) * 32;
    const int wcid = w >> 2;
    const size_t row0 = (size_t)blockIdx.x * 128;

    float* sb = (float*)(sm + OFF_SB);
    float* mk = (float*)(sm + OFF_MK);
    float2* red = (float2*)(sm + OFF_RED);

    const uint32_t ZH = smb + OFF_ZH, ZL = smb + OFF_ZL;
    const uint32_t W0H = smb + OFF_W0H, W0L = smb + OFF_W0L;
    const uint32_t W1H = smb + OFF_W1H, W1L = smb + OFF_W1L;

    // ldmatrix lane offsets (bytes)
    const uint32_t ao0 = (uint32_t)(wr + (lid & 15)) * STR + (uint32_t)(lid >> 4) * 16u;
    const uint32_t ao1 = ao0 + 16u * STR;
    const uint32_t bo0 = (uint32_t)(wc + (lid & 7) + ((lid >> 4) << 3)) * STR +
                         (uint32_t)((lid >> 3) & 1) * 16u;
    const uint32_t bo1 = bo0 + 16u * STR;

    // start weight 0 flowing
    prefetch(W0H, W0L, 0, t);

    // biases + ln_out params
    if (t < 128) {
        sb[t] = __ldg(b_ap + t);           sb[128 + t] = __ldg(b_ag + t);
        sb[256 + t] = __ldg(b_bp + t);     sb[384 + t] = __ldg(b_bg + t);
        sb[512 + t] = __ldg(b_g + t);      sb[640 + t] = __ldg(b_z + t);
        sb[768 + t] = __ldg(ln_out_w + t); sb[896 + t] = __ldg(ln_out_b + t);
    }

    // ---- LN_in: 4 threads/row; write zn hi/lo into padded smem ----
    {
        const int r = t >> 2, q = t & 3;
        const float* zr = z + (row0 + r) * 128 + q * 32;
        float v[32], s = 0.f, s2 = 0.f;
#pragma unroll
        for (int i = 0; i < 8; i++) {
            float4 f = __ldg((const float4*)(zr + 4 * i));
            v[4*i] = f.x; v[4*i+1] = f.y; v[4*i+2] = f.z; v[4*i+3] = f.w;
            s += f.x + f.y + f.z + f.w;
            s2 += f.x*f.x + f.y*f.y + f.z*f.z + f.w*f.w;
        }
        s  += __shfl_xor_sync(~0u, s, 1);  s  += __shfl_xor_sync(~0u, s, 2);
        s2 += __shfl_xor_sync(~0u, s2, 1); s2 += __shfl_xor_sync(~0u, s2, 2);
        float mu = s * (1.f / 128);
        float rstd = rsqrtf(fmaxf(s2 * (1.f / 128) - mu * mu, 0.f) + 1e-5f);
#pragma unroll
        for (int j = 0; j < 4; j++) {
            union { uint4 u; __nv_bfloat16 b[8]; } H, L;
#pragma unroll
            for (int i = 0; i < 8; i++) {
                int c = q * 32 + j * 8 + i;
                float f = (v[j*8+i] - mu) * rstd * __ldg(ln_in_w + c) + __ldg(ln_in_b + c);
                __nv_bfloat16 h = __float2bfloat16(f);
                H.b[i] = h;
                L.b[i] = __float2bfloat16(f - __bfloat162float(h));
            }
            uint32_t off = (uint32_t)r * STR + (uint32_t)(q * 4 + j) * 16u;
            *(uint4*)(sm + off) = H.u;                 // ZH
            *(uint4*)(sm + OFF_ZL + off) = L.u;        // ZL
        }
        if (q == 0) mk[r] = __ldg(mask + row0 + r);
    }

    float xr[32], acc[32];

    // ================= stage 0: xr = zn @ w_ap^T =================
    CP_WAIT0();
    __syncthreads();
    prefetch(W1H, W1L, 1, t);
#pragma unroll
    for (int e = 0; e < 32; e++) xr[e] = 0.f;
    mm(xr, ZH, ZL, W0H, W0L, ao0, ao1, bo0, bo1);

    // ================= stage 1: G = zn @ w_ag^T; xr = a =================
    CP_WAIT0();
    __syncthreads();
    prefetch(W0H, W0L, 2, t);
#pragma unroll
    for (int e = 0; e < 32; e++) acc[e] = 0.f;
    mm(acc, ZH, ZL, W1H, W1L, ao0, ao1, bo0, bo1);
#pragma unroll
    for (int i = 0; i < 4; i++) {
        int row = wr + ((i >> 1) << 4) + ((i & 1) << 3) + quad;
        float m = mk[row];
#pragma unroll
        for (int nb = 0; nb < 4; nb++) {
            int e = ((i >> 1) * 4 + nb) * 4 + (i & 1) * 2;
            int col = wc + nb * 8 + qt * 2;
            xr[e]   = (xr[e]   + sb[col])   * sigm(acc[e]   + sb[128 + col])   * m;
            xr[e+1] = (xr[e+1] + sb[col+1]) * sigm(acc[e+1] + sb[128 + col+1]) * m;
        }
    }

    // ================= stage 2: P = zn @ w_bp^T; xr = a*(P+b)*m =================
    CP_WAIT0();
    __syncthreads();
    prefetch(W1H, W1L, 3, t);
#pragma unroll
    for (int e = 0; e < 32; e++) acc[e] = 0.f;
    mm(acc, ZH, ZL, W0H, W0L, ao0, ao1, bo0, bo1);
#pragma unroll
    for (int i = 0; i < 4; i++) {
        int row = wr + ((i >> 1) << 4) + ((i & 1) << 3) + quad;
        float m = mk[row];
#pragma unroll
        for (int nb = 0; nb < 4; nb++) {
            int e = ((i >> 1) * 4 + nb) * 4 + (i & 1) * 2;
            int col = wc + nb * 8 + qt * 2;
            xr[e]   *= (acc[e]   + sb[256 + col])   * m;
            xr[e+1] *= (acc[e+1] + sb[256 + col+1]) * m;
        }
    }

    // ====== stage 3: G = zn @ w_bg^T; x = xr*sig(G+b); LN partials ======
    CP_WAIT0();
    __syncthreads();
    prefetch(W0H, W0L, 4, t);
#pragma unroll
    for (int e = 0; e < 32; e++) acc[e] = 0.f;
    mm(acc, ZH, ZL, W1H, W1L, ao0, ao1, bo0, bo1);
#pragma unroll
    for (int i = 0; i < 4; i++) {
        int row = wr + ((i >> 1) << 4) + ((i & 1) << 3) + quad;
        float s = 0.f, s2 = 0.f;
#pragma unroll
        for (int nb = 0; nb < 4; nb++) {
            int e = ((i >> 1) * 4 + nb) * 4 + (i & 1) * 2;
            int col = wc + nb * 8 + qt * 2;
            xr[e]   *= sigm(acc[e]   + sb[384 + col]);
            xr[e+1] *= sigm(acc[e+1] + sb[384 + col+1]);
            s  += xr[e] + xr[e+1];
            s2 += xr[e] * xr[e] + xr[e+1] * xr[e+1];
        }
        s  += __shfl_xor_sync(~0u, s, 1);  s  += __shfl_xor_sync(~0u, s, 2);
        s2 += __shfl_xor_sync(~0u, s2, 1); s2 += __shfl_xor_sync(~0u, s2, 2);
        if (qt == 0) red[row * 4 + wcid] = make_float2(s, s2);
    }

    // ================= stage 4: gate = sig(zn @ w_g^T + b_g) =================
    CP_WAIT0();
    __syncthreads();            // red + W visible
    float mu4[4], rs4[4];
#pragma unroll
    for (int i = 0; i < 4; i++) {
        int row = wr + ((i >> 1) << 4) + ((i & 1) << 3) + quad;
        float s = 0.f, s2 = 0.f;
#pragma unroll
        for (int k = 0; k < 4; k++) { float2 p = red[row * 4 + k]; s += p.x; s2 += p.y; }
        mu4[i] = s * (1.f / 128);
        rs4[i] = rsqrtf(fmaxf(s2 * (1.f / 128) - mu4[i] * mu4[i], 0.f) + 1e-5f);
    }
    prefetch(W1H, W1L, 5, t);
#pragma unroll
    for (int e = 0; e < 32; e++) acc[e] = 0.f;
    mm(acc, ZH, ZL, W0H, W0L, ao0, ao1, bo0, bo1);
#pragma unroll
    for (int i = 0; i < 4; i++) {
#pragma unroll
        for (int nb = 0; nb < 4; nb++) {
            int e = ((i >> 1) * 4 + nb) * 4 + (i & 1) * 2;
            int col = wc + nb * 8 + qt * 2;
            acc[e]   = sigm(acc[e]   + sb[512 + col]);
            acc[e+1] = sigm(acc[e+1] + sb[512 + col+1]);
        }
    }
    __syncthreads();            // everyone finished reading zn
    // overwrite zn smem with xn (hi/lo bf16)
#pragma unroll
    for (int i = 0; i < 4; i++) {
        int row = wr + ((i >> 1) << 4) + ((i & 1) << 3) + quad;
#pragma unroll
        for (int nb = 0; nb < 4; nb++) {
            int e = ((i >> 1) * 4 + nb) * 4 + (i & 1) * 2;
            int col = wc + nb * 8 + qt * 2;
            float v0 = (xr[e]   - mu4[i]) * rs4[i] * sb[768 + col]   + sb[896 + col];
            float v1 = (xr[e+1] - mu4[i]) * rs4[i] * sb[768 + col+1] + sb[896 + col+1];
            __nv_bfloat16 h0 = __float2bfloat16(v0);
            __nv_bfloat16 h1 = __float2bfloat16(v1);
            __nv_bfloat16 l0 = __float2bfloat16(v0 - __bfloat162float(h0));
            __nv_bfloat16 l1 = __float2bfloat16(v1 - __bfloat162float(h1));
            uint32_t hh = ((uint32_t)__bfloat16_as_ushort(h1) << 16) | __bfloat16_as_ushort(h0);
            uint32_t ll = ((uint32_t)__bfloat16_as_ushort(l1) << 16) | __bfloat16_as_ushort(l0);
            uint32_t off = (uint32_t)row * STR + (uint32_t)col * 2u;
            *(uint32_t*)(sm + off) = hh;
            *(uint32_t*)(sm + OFF_ZL + off) = ll;
        }
    }

    // ================= stage 5: out = (xn @ w_z^T + b_z) * gate =================
    CP_WAIT0();
    __syncthreads();
#pragma unroll
    for (int e = 0; e < 32; e++) xr[e] = 0.f;
    mm(xr, ZH, ZL, W1H, W1L, ao0, ao1, bo0, bo1);
#pragma unroll
    for (int i = 0; i < 4; i++) {
        int row = wr + ((i >> 1) << 4) + ((i & 1) << 3) + quad;
        float* orow = out + (row0 + row) * 128;
#pragma unroll
        for (int nb = 0; nb < 4; nb++) {
            int e = ((i >> 1) * 4 + nb) * 4 + (i & 1) * 2;
            int col = wc + nb * 8 + qt * 2;
            float2 o;
            o.x = (xr[e]   + sb[640 + col])   * acc[e];
            o.y = (xr[e+1] + sb[640 + col+1]) * acc[e+1];
            *(float2*)(orow + col) = o;
        }
    }
}

extern "C" void kernel_launch(void* const* d_in, const int* in_sizes, int n_in,
                              void* d_out, int out_size) {
    const float* z        = (const float*)d_in[0];
    const float* mask     = (const float*)d_in[1];
    const float* w_ap     = (const float*)d_in[2];
    const float* b_ap     = (const float*)d_in[3];
    const float* w_bp     = (const float*)d_in[4];
    const float* b_bp     = (const float*)d_in[5];
    const float* w_ag     = (const float*)d_in[6];
    const float* b_ag     = (const float*)d_in[7];
    const float* w_bg     = (const float*)d_in[8];
    const float* b_bg     = (const float*)d_in[9];
    const float* w_g      = (const float*)d_in[10];
    const float* b_g      = (const float*)d_in[11];
    const float* w_z      = (const float*)d_in[12];
    const float* b_z      = (const float*)d_in[13];
    const float* ln_in_w  = (const float*)d_in[14];
    const float* ln_in_b  = (const float*)d_in[15];
    const float* ln_out_w = (const float*)d_in[16];
    const float* ln_out_b = (const float*)d_in[17];
    float* out = (float*)d_out;

    const int rows = in_sizes[1];      // B*N*N
    const int nblocks = rows / 128;    // 1152

    static int configured = 0;
    if (!configured) {
        cudaFuncSetAttribute(tmu_kernel, cudaFuncAttributeMaxDynamicSharedMemorySize, SMEM_BYTES);
        configured = 1;
    }

    // stage order in g_w: 0=w_ap 1=w_ag 2=w_bp 3=w_bg 4=w_g 5=w_z
    kPrep<<<6, 512>>>(w_ap, w_ag, w_bp, w_bg, w_g, w_z);
    tmu_kernel<<<nblocks, NT, SMEM_BYTES>>>(z, mask,
                                            b_ap, b_ag, b_bp, b_bg, b_g, b_z,
                                            ln_in_w, ln_in_b, ln_out_w, ln_out_b,
                                            out);
}

// round 4
// speedup vs baseline: 2.1280x; 1.0542x over previous
#include <cuda_runtime.h>
#include <cuda_bf16.h>
#include <stdint.h>

// TriangleMultiplicativeUpdate, fused, mma.sync m16n8k16 bf16 with 3-term
// hi/lo split (fp32 accum). Round 4: 64-row tiles / 256 threads so TWO CTAs
// fit per SM (smem 110848B each) — cross-CTA overlap hides the per-stage
// cp.async weight loads, barriers, and LN/epilogue scalar work that limited
// tensor-pipe utilization to 45% with one fat CTA.

#define NT 256
#define STR 272u   // smem row stride in bytes (136 bf16): conflict-free ldmatrix

#define OFF_ZH  0u            // zn hi: 64 x 272
#define OFF_ZL  17408u        // zn lo
#define OFF_WH  34816u        // weight hi: 128 x 272
#define OFF_WL  69632u        // weight lo
#define OFF_SB  104448u       // 8 x 128 floats (biases, ln_out w/b)
#define OFF_MK  108544u       // 64 floats (mask)
#define OFF_RED 108800u       // 64 x 4 float2 (LN_out partials)
#define SMEM_BYTES 110848

// weights as bf16 hi/lo, linear [n][k]; 0=w_ap 1=w_ag 2=w_bp 3=w_bg 4=w_g 5=w_z
__device__ __align__(16) __nv_bfloat16 g_w[6][2][128 * 128];

__device__ __forceinline__ uint32_t s2u(const void* p) {
    uint32_t a;
    asm("{ .reg .u64 t; cvta.to.shared.u64 t, %1; cvt.u32.u64 %0, t; }" : "=r"(a) : "l"(p));
    return a;
}

#define LDSM4(r, a) \
    asm volatile("ldmatrix.sync.aligned.m8n8.x4.shared.b16 {%0,%1,%2,%3}, [%4];" \
        : "=r"((r)[0]), "=r"((r)[1]), "=r"((r)[2]), "=r"((r)[3]) : "r"(a))

#define MMAOP(d, a, b0, b1) \
    asm volatile("mma.sync.aligned.m16n8k16.row.col.f32.bf16.bf16.f32 " \
        "{%0,%1,%2,%3}, {%4,%5,%6,%7}, {%8,%9}, {%0,%1,%2,%3};" \
        : "+f"((d)[0]), "+f"((d)[1]), "+f"((d)[2]), "+f"((d)[3]) \
        : "r"((a)[0]), "r"((a)[1]), "r"((a)[2]), "r"((a)[3]), "r"(b0), "r"(b1))

#define CPA16(dst, src) \
    asm volatile("cp.async.cg.shared.global [%0], [%1], 16;" :: "r"(dst), "l"(src))
#define CP_COMMIT() asm volatile("cp.async.commit_group;" ::: "memory")
#define CP_WAIT0()  asm volatile("cp.async.wait_group 0;" ::: "memory")

__device__ __forceinline__ float sigm(float x) { return 1.0f / (1.0f + __expf(-x)); }

// 64x128x128 (per-CTA) matmul slice, 3-term bf16 split; acc += zn @ W^T
__device__ __forceinline__ void mm(float* acc, uint32_t ah, uint32_t al,
                                   uint32_t bh, uint32_t bl,
                                   uint32_t ao0, uint32_t ao1,
                                   uint32_t bo0, uint32_t bo1) {
#pragma unroll 1
    for (int k = 0; k < 8; k++) {
        uint32_t ko = (uint32_t)k * 32u;
        uint32_t Ah0[4], Ah1[4], Al0[4], Al1[4];
        uint32_t Bh0[4], Bh1[4], Bl0[4], Bl1[4];
        LDSM4(Ah0, ah + ao0 + ko); LDSM4(Ah1, ah + ao1 + ko);
        LDSM4(Al0, al + ao0 + ko); LDSM4(Al1, al + ao1 + ko);
        LDSM4(Bh0, bh + bo0 + ko); LDSM4(Bh1, bh + bo1 + ko);
        LDSM4(Bl0, bl + bo0 + ko); LDSM4(Bl1, bl + bo1 + ko);
        MMAOP(acc + 0,  Ah0, Bh0[0], Bh0[1]); MMAOP(acc + 4,  Ah0, Bh0[2], Bh0[3]);
        MMAOP(acc + 8,  Ah0, Bh1[0], Bh1[1]); MMAOP(acc + 12, Ah0, Bh1[2], Bh1[3]);
        MMAOP(acc + 16, Ah1, Bh0[0], Bh0[1]); MMAOP(acc + 20, Ah1, Bh0[2], Bh0[3]);
        MMAOP(acc + 24, Ah1, Bh1[0], Bh1[1]); MMAOP(acc + 28, Ah1, Bh1[2], Bh1[3]);
        MMAOP(acc + 0,  Ah0, Bl0[0], Bl0[1]); MMAOP(acc + 4,  Ah0, Bl0[2], Bl0[3]);
        MMAOP(acc + 8,  Ah0, Bl1[0], Bl1[1]); MMAOP(acc + 12, Ah0, Bl1[2], Bl1[3]);
        MMAOP(acc + 16, Ah1, Bl0[0], Bl0[1]); MMAOP(acc + 20, Ah1, Bl0[2], Bl0[3]);
        MMAOP(acc + 24, Ah1, Bl1[0], Bl1[1]); MMAOP(acc + 28, Ah1, Bl1[2], Bl1[3]);
        MMAOP(acc + 0,  Al0, Bh0[0], Bh0[1]); MMAOP(acc + 4,  Al0, Bh0[2], Bh0[3]);
        MMAOP(acc + 8,  Al0, Bh1[0], Bh1[1]); MMAOP(acc + 12, Al0, Bh1[2], Bh1[3]);
        MMAOP(acc + 16, Al1, Bh0[0], Bh0[1]); MMAOP(acc + 20, Al1, Bh0[2], Bh0[3]);
        MMAOP(acc + 24, Al1, Bh1[0], Bh1[1]); MMAOP(acc + 28, Al1, Bh1[2], Bh1[3]);
    }
}

// async-copy one weight (hi+lo, 64KB linear) into the padded smem slot
__device__ __forceinline__ void prefetch(uint32_t dstH, uint32_t dstL, int widx, int t) {
    const char* sh = (const char*)g_w[widx][0];
    const char* sl = (const char*)g_w[widx][1];
#pragma unroll
    for (int i = 0; i < 8; i++) {
        int cid = t + i * NT;                  // 2048 16B chunks per matrix
        uint32_t d = (uint32_t)(cid >> 4) * STR + (uint32_t)(cid & 15) * 16u;
        CPA16(dstH + d, sh + (size_t)cid * 16);
        CPA16(dstL + d, sl + (size_t)cid * 16);
    }
    CP_COMMIT();
}

__global__ void kPrep(const float* __restrict__ w0, const float* __restrict__ w1,
                      const float* __restrict__ w2, const float* __restrict__ w3,
                      const float* __restrict__ w4, const float* __restrict__ w5) {
    const float* w;
    switch (blockIdx.x) {
        case 0: w = w0; break; case 1: w = w1; break; case 2: w = w2; break;
        case 3: w = w3; break; case 4: w = w4; break; default: w = w5; break;
    }
    __nv_bfloat16* h = g_w[blockIdx.x][0];
    __nv_bfloat16* l = g_w[blockIdx.x][1];
    for (int i = threadIdx.x; i < 128 * 128; i += blockDim.x) {
        float v = __ldg(w + i);
        __nv_bfloat16 hh = __float2bfloat16(v);
        h[i] = hh;
        l[i] = __float2bfloat16(v - __bfloat162float(hh));
    }
}

__global__ void __launch_bounds__(NT, 2)
tmu_kernel(const float* __restrict__ z, const float* __restrict__ mask,
           const float* __restrict__ b_ap, const float* __restrict__ b_ag,
           const float* __restrict__ b_bp, const float* __restrict__ b_bg,
           const float* __restrict__ b_g,  const float* __restrict__ b_z,
           const float* __restrict__ ln_in_w,  const float* __restrict__ ln_in_b,
           const float* __restrict__ ln_out_w, const float* __restrict__ ln_out_b,
           float* __restrict__ out) {
    extern __shared__ char sm[];
    const uint32_t smb = s2u(sm);
    const int t = threadIdx.x;
    const int w = t >> 5, lid = t & 31;
    const int quad = lid >> 2, qt = lid & 3;
    const int wr = (w & 1) * 32, wc = (w >> 1) * 32;
    const int wcid = w >> 1;
    const size_t row0 = (size_t)blockIdx.x * 64;

    float* sb = (float*)(sm + OFF_SB);
    float* mk = (float*)(sm + OFF_MK);
    float2* red = (float2*)(sm + OFF_RED);

    const uint32_t ZH = smb + OFF_ZH, ZL = smb + OFF_ZL;
    const uint32_t WH = smb + OFF_WH, WL = smb + OFF_WL;

    // ldmatrix lane offsets (bytes)
    const uint32_t ao0 = (uint32_t)(wr + (lid & 15)) * STR + (uint32_t)(lid >> 4) * 16u;
    const uint32_t ao1 = ao0 + 16u * STR;
    const uint32_t bo0 = (uint32_t)(wc + (lid & 7) + ((lid >> 4) << 3)) * STR +
                         (uint32_t)((lid >> 3) & 1) * 16u;
    const uint32_t bo1 = bo0 + 16u * STR;

    // start weight 0 flowing immediately
    prefetch(WH, WL, 0, t);

    // biases + ln_out params
    if (t < 128) {
        sb[t] = __ldg(b_ap + t);           sb[128 + t] = __ldg(b_ag + t);
        sb[256 + t] = __ldg(b_bp + t);     sb[384 + t] = __ldg(b_bg + t);
        sb[512 + t] = __ldg(b_g + t);      sb[640 + t] = __ldg(b_z + t);
        sb[768 + t] = __ldg(ln_out_w + t); sb[896 + t] = __ldg(ln_out_b + t);
    }

    // ---- LN_in: 4 threads/row over 64 rows; write zn hi/lo ----
    {
        const int r = t >> 2, q = t & 3;
        const float* zr = z + (row0 + r) * 128 + q * 32;
        float v[32], s = 0.f, s2 = 0.f;
#pragma unroll
        for (int i = 0; i < 8; i++) {
            float4 f = __ldg((const float4*)(zr + 4 * i));
            v[4*i] = f.x; v[4*i+1] = f.y; v[4*i+2] = f.z; v[4*i+3] = f.w;
            s += f.x + f.y + f.z + f.w;
            s2 += f.x*f.x + f.y*f.y + f.z*f.z + f.w*f.w;
        }
        s  += __shfl_xor_sync(~0u, s, 1);  s  += __shfl_xor_sync(~0u, s, 2);
        s2 += __shfl_xor_sync(~0u, s2, 1); s2 += __shfl_xor_sync(~0u, s2, 2);
        float mu = s * (1.f / 128);
        float rstd = rsqrtf(fmaxf(s2 * (1.f / 128) - mu * mu, 0.f) + 1e-5f);
#pragma unroll
        for (int j = 0; j < 4; j++) {
            union { uint4 u; __nv_bfloat16 b[8]; } H, L;
#pragma unroll
            for (int i = 0; i < 8; i++) {
                int c = q * 32 + j * 8 + i;
                float f = (v[j*8+i] - mu) * rstd * __ldg(ln_in_w + c) + __ldg(ln_in_b + c);
                __nv_bfloat16 h = __float2bfloat16(f);
                H.b[i] = h;
                L.b[i] = __float2bfloat16(f - __bfloat162float(h));
            }
            uint32_t off = (uint32_t)r * STR + (uint32_t)(q * 4 + j) * 16u;
            *(uint4*)(sm + off) = H.u;                 // ZH
            *(uint4*)(sm + OFF_ZL + off) = L.u;        // ZL
        }
        if (q == 0) mk[r] = __ldg(mask + row0 + r);
    }

    float xr[32], acc[32];

    // ================= stage 0: xr = zn @ w_ap^T =================
    CP_WAIT0();
    __syncthreads();
#pragma unroll
    for (int e = 0; e < 32; e++) xr[e] = 0.f;
    mm(xr, ZH, ZL, WH, WL, ao0, ao1, bo0, bo1);

    // ================= stage 1: G = zn @ w_ag^T; xr = a =================
    __syncthreads();                       // all warps done reading W
    prefetch(WH, WL, 1, t);
    CP_WAIT0();
    __syncthreads();
#pragma unroll
    for (int e = 0; e < 32; e++) acc[e] = 0.f;
    mm(acc, ZH, ZL, WH, WL, ao0, ao1, bo0, bo1);
#pragma unroll
    for (int i = 0; i < 4; i++) {
        int row = wr + ((i >> 1) << 4) + ((i & 1) << 3) + quad;
        float m = mk[row];
#pragma unroll
        for (int nb = 0; nb < 4; nb++) {
            int e = ((i >> 1) * 4 + nb) * 4 + (i & 1) * 2;
            int col = wc + nb * 8 + qt * 2;
            xr[e]   = (xr[e]   + sb[col])   * sigm(acc[e]   + sb[128 + col])   * m;
            xr[e+1] = (xr[e+1] + sb[col+1]) * sigm(acc[e+1] + sb[128 + col+1]) * m;
        }
    }

    // ================= stage 2: P = zn @ w_bp^T; xr *= (P+b)*m =================
    __syncthreads();
    prefetch(WH, WL, 2, t);
    CP_WAIT0();
    __syncthreads();
#pragma unroll
    for (int e = 0; e < 32; e++) acc[e] = 0.f;
    mm(acc, ZH, ZL, WH, WL, ao0, ao1, bo0, bo1);
#pragma unroll
    for (int i = 0; i < 4; i++) {
        int row = wr + ((i >> 1) << 4) + ((i & 1) << 3) + quad;
        float m = mk[row];
#pragma unroll
        for (int nb = 0; nb < 4; nb++) {
            int e = ((i >> 1) * 4 + nb) * 4 + (i & 1) * 2;
            int col = wc + nb * 8 + qt * 2;
            xr[e]   *= (acc[e]   + sb[256 + col])   * m;
            xr[e+1] *= (acc[e+1] + sb[256 + col+1]) * m;
        }
    }

    // ====== stage 3: G = zn @ w_bg^T; x = xr*sig(G+b); LN partials ======
    __syncthreads();
    prefetch(WH, WL, 3, t);
    CP_WAIT0();
    __syncthreads();
#pragma unroll
    for (int e = 0; e < 32; e++) acc[e] = 0.f;
    mm(acc, ZH, ZL, WH, WL, ao0, ao1, bo0, bo1);
#pragma unroll
    for (int i = 0; i < 4; i++) {
        int row = wr + ((i >> 1) << 4) + ((i & 1) << 3) + quad;
        float s = 0.f, s2 = 0.f;
#pragma unroll
        for (int nb = 0; nb < 4; nb++) {
            int e = ((i >> 1) * 4 + nb) * 4 + (i & 1) * 2;
            int col = wc + nb * 8 + qt * 2;
            xr[e]   *= sigm(acc[e]   + sb[384 + col]);
            xr[e+1] *= sigm(acc[e+1] + sb[384 + col+1]);
            s  += xr[e] + xr[e+1];
            s2 += xr[e] * xr[e] + xr[e+1] * xr[e+1];
        }
        s  += __shfl_xor_sync(~0u, s, 1);  s  += __shfl_xor_sync(~0u, s, 2);
        s2 += __shfl_xor_sync(~0u, s2, 1); s2 += __shfl_xor_sync(~0u, s2, 2);
        if (qt == 0) red[row * 4 + wcid] = make_float2(s, s2);
    }

    // ================= stage 4: gate = sig(zn @ w_g^T + b_g) =================
    __syncthreads();                       // red visible, W free
    prefetch(WH, WL, 4, t);
    float mu4[4], rs4[4];
#pragma unroll
    for (int i = 0; i < 4; i++) {
        int row = wr + ((i >> 1) << 4) + ((i & 1) << 3) + quad;
        float s = 0.f, s2 = 0.f;
#pragma unroll
        for (int k = 0; k < 4; k++) { float2 p = red[row * 4 + k]; s += p.x; s2 += p.y; }
        mu4[i] = s * (1.f / 128);
        rs4[i] = rsqrtf(fmaxf(s2 * (1.f / 128) - mu4[i] * mu4[i], 0.f) + 1e-5f);
    }
    CP_WAIT0();
    __syncthreads();
#pragma unroll
    for (int e = 0; e < 32; e++) acc[e] = 0.f;
    mm(acc, ZH, ZL, WH, WL, ao0, ao1, bo0, bo1);
#pragma unroll
    for (int i = 0; i < 4; i++) {
#pragma unroll
        for (int nb = 0; nb < 4; nb++) {
            int e = ((i >> 1) * 4 + nb) * 4 + (i & 1) * 2;
            int col = wc + nb * 8 + qt * 2;
            acc[e]   = sigm(acc[e]   + sb[512 + col]);
            acc[e+1] = sigm(acc[e+1] + sb[512 + col+1]);
        }
    }
    __syncthreads();            // everyone finished reading zn and W
    prefetch(WH, WL, 5, t);
    // overwrite zn smem with xn (hi/lo bf16)
#pragma unroll
    for (int i = 0; i < 4; i++) {
        int row = wr + ((i >> 1) << 4) + ((i & 1) << 3) + quad;
#pragma unroll
        for (int nb = 0; nb < 4; nb++) {
            int e = ((i >> 1) * 4 + nb) * 4 + (i & 1) * 2;
            int col = wc + nb * 8 + qt * 2;
            float v0 = (xr[e]   - mu4[i]) * rs4[i] * sb[768 + col]   + sb[896 + col];
            float v1 = (xr[e+1] - mu4[i]) * rs4[i] * sb[768 + col+1] + sb[896 + col+1];
            __nv_bfloat16 h0 = __float2bfloat16(v0);
            __nv_bfloat16 h1 = __float2bfloat16(v1);
            __nv_bfloat16 l0 = __float2bfloat16(v0 - __bfloat162float(h0));
            __nv_bfloat16 l1 = __float2bfloat16(v1 - __bfloat162float(h1));
            uint32_t hh = ((uint32_t)__bfloat16_as_ushort(h1) << 16) | __bfloat16_as_ushort(h0);
            uint32_t ll = ((uint32_t)__bfloat16_as_ushort(l1) << 16) | __bfloat16_as_ushort(l0);
            uint32_t off = (uint32_t)row * STR + (uint32_t)col * 2u;
            *(uint32_t*)(sm + off) = hh;
            *(uint32_t*)(sm + OFF_ZL + off) = ll;
        }
    }

    // ================= stage 5: out = (xn @ w_z^T + b_z) * gate =================
    CP_WAIT0();
    __syncthreads();
#pragma unroll
    for (int e = 0; e < 32; e++) xr[e] = 0.f;
    mm(xr, ZH, ZL, WH, WL, ao0, ao1, bo0, bo1);
#pragma unroll
    for (int i = 0; i < 4; i++) {
        int row = wr + ((i >> 1) << 4) + ((i & 1) << 3) + quad;
        float* orow = out + (row0 + row) * 128;
#pragma unroll
        for (int nb = 0; nb < 4; nb++) {
            int e = ((i >> 1) * 4 + nb) * 4 + (i & 1) * 2;
            int col = wc + nb * 8 + qt * 2;
            float2 o;
            o.x = (xr[e]   + sb[640 + col])   * acc[e];
            o.y = (xr[e+1] + sb[640 + col+1]) * acc[e+1];
            *(float2*)(orow + col) = o;
        }
    }
}

extern "C" void kernel_launch(void* const* d_in, const int* in_sizes, int n_in,
                              void* d_out, int out_size) {
    const float* z        = (const float*)d_in[0];
    const float* mask     = (const float*)d_in[1];
    const float* w_ap     = (const float*)d_in[2];
    const float* b_ap     = (const float*)d_in[3];
    const float* w_bp     = (const float*)d_in[4];
    const float* b_bp     = (const float*)d_in[5];
    const float* w_ag     = (const float*)d_in[6];
    const float* b_ag     = (const float*)d_in[7];
    const float* w_bg     = (const float*)d_in[8];
    const float* b_bg     = (const float*)d_in[9];
    const float* w_g      = (const float*)d_in[10];
    const float* b_g      = (const float*)d_in[11];
    const float* w_z      = (const float*)d_in[12];
    const float* b_z      = (const float*)d_in[13];
    const float* ln_in_w  = (const float*)d_in[14];
    const float* ln_in_b  = (const float*)d_in[15];
    const float* ln_out_w = (const float*)d_in[16];
    const float* ln_out_b = (const float*)d_in[17];
    float* out = (float*)d_out;

    const int rows = in_sizes[1];      // B*N*N
    const int nblocks = rows / 64;     // 2304

    static int configured = 0;
    if (!configured) {
        cudaFuncSetAttribute(tmu_kernel, cudaFuncAttributeMaxDynamicSharedMemorySize, SMEM_BYTES);
        configured = 1;
    }

    // stage order in g_w: 0=w_ap 1=w_ag 2=w_bp 3=w_bg 4=w_g 5=w_z
    kPrep<<<6, 512>>>(w_ap, w_ag, w_bp, w_bg, w_g, w_z);
    tmu_kernel<<<nblocks, NT, SMEM_BYTES>>>(z, mask,
                                            b_ap, b_ag, b_bp, b_bg, b_g, b_z,
                                            ln_in_w, ln_in_b, ln_out_w, ln_out_b,
                                            out);
}

// round 5
// speedup vs baseline: 2.1695x; 1.0195x over previous
#include <cuda_runtime.h>
#include <cuda_bf16.h>
#include <stdint.h>

// TriangleMultiplicativeUpdate, fused, mma.sync m16n8k16 bf16 with 3-term
// hi/lo split (fp32 accum). Round 5: per-stage passes reordered as
// (hh+lh on W_hi) then (hl on W_lo) so each k-loop is fully unrolled
// (ptxas software-pipelines the ldmatrix loads), and the next stage's
// weight halves stream in via cp.async groups while the current half is
// being consumed — removing the exposed per-stage load waits.

#define NT 256
#define STR 272u   // smem row stride in bytes (136 bf16): conflict-free ldmatrix

#define OFF_ZH  0u            // zn hi: 64 x 272
#define OFF_ZL  17408u        // zn lo
#define OFF_WH  34816u        // weight hi: 128 x 272
#define OFF_WL  69632u        // weight lo
#define OFF_SB  104448u       // 8 x 128 floats (biases, ln_out w/b)
#define OFF_MK  108544u       // 64 floats (mask)
#define OFF_RED 108800u       // 64 x 4 float2 (LN_out partials)
#define SMEM_BYTES 110848

// weights as bf16 hi/lo, linear [n][k]; 0=w_ap 1=w_ag 2=w_bp 3=w_bg 4=w_g 5=w_z
__device__ __align__(16) __nv_bfloat16 g_w[6][2][128 * 128];

__device__ __forceinline__ uint32_t s2u(const void* p) {
    uint32_t a;
    asm("{ .reg .u64 t; cvta.to.shared.u64 t, %1; cvt.u32.u64 %0, t; }" : "=r"(a) : "l"(p));
    return a;
}

#define LDSM4(r, a) \
    asm volatile("ldmatrix.sync.aligned.m8n8.x4.shared.b16 {%0,%1,%2,%3}, [%4];" \
        : "=r"((r)[0]), "=r"((r)[1]), "=r"((r)[2]), "=r"((r)[3]) : "r"(a))

#define MMAOP(d, a, b0, b1) \
    asm volatile("mma.sync.aligned.m16n8k16.row.col.f32.bf16.bf16.f32 " \
        "{%0,%1,%2,%3}, {%4,%5,%6,%7}, {%8,%9}, {%0,%1,%2,%3};" \
        : "+f"((d)[0]), "+f"((d)[1]), "+f"((d)[2]), "+f"((d)[3]) \
        : "r"((a)[0]), "r"((a)[1]), "r"((a)[2]), "r"((a)[3]), "r"(b0), "r"(b1))

#define CPA16(dst, src) \
    asm volatile("cp.async.cg.shared.global [%0], [%1], 16;" :: "r"(dst), "l"(src))
#define CP_COMMIT() asm volatile("cp.async.commit_group;" ::: "memory")
#define CP_WAIT0()  asm volatile("cp.async.wait_group 0;" ::: "memory")
#define CP_WAIT1()  asm volatile("cp.async.wait_group 1;" ::: "memory")

__device__ __forceinline__ float sigm(float x) { return 1.0f / (1.0f + __expf(-x)); }

// passes hh + lh: acc += Ah@Bh^T + Al@Bh^T   (reads W hi slot only)
__device__ __forceinline__ void mm_hhlh(float* acc, uint32_t zh, uint32_t zl,
                                        uint32_t wh,
                                        uint32_t ao0, uint32_t ao1,
                                        uint32_t bo0, uint32_t bo1) {
#pragma unroll
    for (int k = 0; k < 8; k++) {
        uint32_t ko = (uint32_t)k * 32u;
        uint32_t Ah0[4], Ah1[4], Al0[4], Al1[4], Bh0[4], Bh1[4];
        LDSM4(Ah0, zh + ao0 + ko); LDSM4(Ah1, zh + ao1 + ko);
        LDSM4(Al0, zl + ao0 + ko); LDSM4(Al1, zl + ao1 + ko);
        LDSM4(Bh0, wh + bo0 + ko); LDSM4(Bh1, wh + bo1 + ko);
        MMAOP(acc + 0,  Ah0, Bh0[0], Bh0[1]); MMAOP(acc + 4,  Ah0, Bh0[2], Bh0[3]);
        MMAOP(acc + 8,  Ah0, Bh1[0], Bh1[1]); MMAOP(acc + 12, Ah0, Bh1[2], Bh1[3]);
        MMAOP(acc + 16, Ah1, Bh0[0], Bh0[1]); MMAOP(acc + 20, Ah1, Bh0[2], Bh0[3]);
        MMAOP(acc + 24, Ah1, Bh1[0], Bh1[1]); MMAOP(acc + 28, Ah1, Bh1[2], Bh1[3]);
        MMAOP(acc + 0,  Al0, Bh0[0], Bh0[1]); MMAOP(acc + 4,  Al0, Bh0[2], Bh0[3]);
        MMAOP(acc + 8,  Al0, Bh1[0], Bh1[1]); MMAOP(acc + 12, Al0, Bh1[2], Bh1[3]);
        MMAOP(acc + 16, Al1, Bh0[0], Bh0[1]); MMAOP(acc + 20, Al1, Bh0[2], Bh0[3]);
        MMAOP(acc + 24, Al1, Bh1[0], Bh1[1]); MMAOP(acc + 28, Al1, Bh1[2], Bh1[3]);
    }
}

// pass hl: acc += Ah@Bl^T   (reads W lo slot only)
__device__ __forceinline__ void mm_hl(float* acc, uint32_t zh, uint32_t wl,
                                      uint32_t ao0, uint32_t ao1,
                                      uint32_t bo0, uint32_t bo1) {
#pragma unroll
    for (int k = 0; k < 8; k++) {
        uint32_t ko = (uint32_t)k * 32u;
        uint32_t Ah0[4], Ah1[4], Bl0[4], Bl1[4];
        LDSM4(Ah0, zh + ao0 + ko); LDSM4(Ah1, zh + ao1 + ko);
        LDSM4(Bl0, wl + bo0 + ko); LDSM4(Bl1, wl + bo1 + ko);
        MMAOP(acc + 0,  Ah0, Bl0[0], Bl0[1]); MMAOP(acc + 4,  Ah0, Bl0[2], Bl0[3]);
        MMAOP(acc + 8,  Ah0, Bl1[0], Bl1[1]); MMAOP(acc + 12, Ah0, Bl1[2], Bl1[3]);
        MMAOP(acc + 16, Ah1, Bl0[0], Bl0[1]); MMAOP(acc + 20, Ah1, Bl0[2], Bl0[3]);
        MMAOP(acc + 24, Ah1, Bl1[0], Bl1[1]); MMAOP(acc + 28, Ah1, Bl1[2], Bl1[3]);
    }
}

// async-copy ONE weight matrix half (32KB) into a padded smem slot; one group
__device__ __forceinline__ void prefetch_half(uint32_t dst, const __nv_bfloat16* src, int t) {
    const char* s = (const char*)src;
#pragma unroll
    for (int i = 0; i < 8; i++) {
        int cid = t + i * NT;                  // 2048 16B chunks
        uint32_t d = (uint32_t)(cid >> 4) * STR + (uint32_t)(cid & 15) * 16u;
        CPA16(dst + d, s + (size_t)cid * 16);
    }
    CP_COMMIT();
}

__global__ void kPrep(const float* __restrict__ w0, const float* __restrict__ w1,
                      const float* __restrict__ w2, const float* __restrict__ w3,
                      const float* __restrict__ w4, const float* __restrict__ w5) {
    const float* w;
    switch (blockIdx.x) {
        case 0: w = w0; break; case 1: w = w1; break; case 2: w = w2; break;
        case 3: w = w3; break; case 4: w = w4; break; default: w = w5; break;
    }
    __nv_bfloat16* h = g_w[blockIdx.x][0];
    __nv_bfloat16* l = g_w[blockIdx.x][1];
    for (int i = threadIdx.x; i < 128 * 128; i += blockDim.x) {
        float v = __ldg(w + i);
        __nv_bfloat16 hh = __float2bfloat16(v);
        h[i] = hh;
        l[i] = __float2bfloat16(v - __bfloat162float(hh));
    }
}

__global__ void __launch_bounds__(NT, 2)
tmu_kernel(const float* __restrict__ z, const float* __restrict__ mask,
           const float* __restrict__ b_ap, const float* __restrict__ b_ag,
           const float* __restrict__ b_bp, const float* __restrict__ b_bg,
           const float* __restrict__ b_g,  const float* __restrict__ b_z,
           const float* __restrict__ ln_in_w,  const float* __restrict__ ln_in_b,
           const float* __restrict__ ln_out_w, const float* __restrict__ ln_out_b,
           float* __restrict__ out) {
    extern __shared__ char sm[];
    const uint32_t smb = s2u(sm);
    const int t = threadIdx.x;
    const int w = t >> 5, lid = t & 31;
    const int quad = lid >> 2, qt = lid & 3;
    const int wr = (w & 1) * 32, wc = (w >> 1) * 32;
    const int wcid = w >> 1;
    const size_t row0 = (size_t)blockIdx.x * 64;

    float* sb = (float*)(sm + OFF_SB);
    float* mk = (float*)(sm + OFF_MK);
    float2* red = (float2*)(sm + OFF_RED);

    const uint32_t ZH = smb + OFF_ZH, ZL = smb + OFF_ZL;
    const uint32_t WH = smb + OFF_WH, WL = smb + OFF_WL;

    const uint32_t ao0 = (uint32_t)(wr + (lid & 15)) * STR + (uint32_t)(lid >> 4) * 16u;
    const uint32_t ao1 = ao0 + 16u * STR;
    const uint32_t bo0 = (uint32_t)(wc + (lid & 7) + ((lid >> 4) << 3)) * STR +
                         (uint32_t)((lid >> 3) & 1) * 16u;
    const uint32_t bo1 = bo0 + 16u * STR;

    // bootstrap: start both halves of weight 0 (two cp groups in flight)
    prefetch_half(WH, g_w[0][0], t);
    prefetch_half(WL, g_w[0][1], t);

    if (t < 128) {
        sb[t] = __ldg(b_ap + t);           sb[128 + t] = __ldg(b_ag + t);
        sb[256 + t] = __ldg(b_bp + t);     sb[384 + t] = __ldg(b_bg + t);
        sb[512 + t] = __ldg(b_g + t);      sb[640 + t] = __ldg(b_z + t);
        sb[768 + t] = __ldg(ln_out_w + t); sb[896 + t] = __ldg(ln_out_b + t);
    }

    // ---- LN_in: 4 threads/row over 64 rows; write zn hi/lo ----
    {
        const int r = t >> 2, q = t & 3;
        const float* zr = z + (row0 + r) * 128 + q * 32;
        float v[32], s = 0.f, s2 = 0.f;
#pragma unroll
        for (int i = 0; i < 8; i++) {
            float4 f = __ldg((const float4*)(zr + 4 * i));
            v[4*i] = f.x; v[4*i+1] = f.y; v[4*i+2] = f.z; v[4*i+3] = f.w;
            s += f.x + f.y + f.z + f.w;
            s2 += f.x*f.x + f.y*f.y + f.z*f.z + f.w*f.w;
        }
        s  += __shfl_xor_sync(~0u, s, 1);  s  += __shfl_xor_sync(~0u, s, 2);
        s2 += __shfl_xor_sync(~0u, s2, 1); s2 += __shfl_xor_sync(~0u, s2, 2);
        float mu = s * (1.f / 128);
        float rstd = rsqrtf(fmaxf(s2 * (1.f / 128) - mu * mu, 0.f) + 1e-5f);
#pragma unroll
        for (int j = 0; j < 4; j++) {
            union { uint4 u; __nv_bfloat16 b[8]; } H, L;
#pragma unroll
            for (int i = 0; i < 8; i++) {
                int c = q * 32 + j * 8 + i;
                float f = (v[j*8+i] - mu) * rstd * __ldg(ln_in_w + c) + __ldg(ln_in_b + c);
                __nv_bfloat16 h = __float2bfloat16(f);
                H.b[i] = h;
                L.b[i] = __float2bfloat16(f - __bfloat162float(h));
            }
            uint32_t off = (uint32_t)r * STR + (uint32_t)(q * 4 + j) * 16u;
            *(uint4*)(sm + off) = H.u;
            *(uint4*)(sm + OFF_ZL + off) = L.u;
        }
        if (q == 0) mk[r] = __ldg(mask + row0 + r);
    }

    float xr[32], acc[32];

    // entry invariant per stage s: W_hi(s) landed CTA-wide; W_lo(s) = the one
    // outstanding cp group (or landed).

    CP_WAIT1();            // Wh(0) done; Wl(0) in flight
    __syncthreads();

    // ================= stage 0: xr = zn @ w_ap^T =================
#pragma unroll
    for (int e = 0; e < 32; e++) xr[e] = 0.f;
    mm_hhlh(xr, ZH, ZL, WH, ao0, ao1, bo0, bo1);
    __syncthreads();                         // WH free
    prefetch_half(WH, g_w[1][0], t);         // Wh(1) ->
    CP_WAIT1();                              // Wl(0) done
    __syncthreads();
    mm_hl(xr, ZH, WL, ao0, ao1, bo0, bo1);
    __syncthreads();                         // WL free
    prefetch_half(WL, g_w[1][1], t);         // Wl(1) ->
    CP_WAIT1();                              // Wh(1) done
    __syncthreads();

    // ================= stage 1: acc = zn @ w_ag^T; xr = a =================
#pragma unroll
    for (int e = 0; e < 32; e++) acc[e] = 0.f;
    mm_hhlh(acc, ZH, ZL, WH, ao0, ao1, bo0, bo1);
    __syncthreads();
    prefetch_half(WH, g_w[2][0], t);
    CP_WAIT1();
    __syncthreads();
    mm_hl(acc, ZH, WL, ao0, ao1, bo0, bo1);
    __syncthreads();
    prefetch_half(WL, g_w[2][1], t);
#pragma unroll
    for (int i = 0; i < 4; i++) {
        int row = wr + ((i >> 1) << 4) + ((i & 1) << 3) + quad;
        float m = mk[row];
#pragma unroll
        for (int nb = 0; nb < 4; nb++) {
            int e = ((i >> 1) * 4 + nb) * 4 + (i & 1) * 2;
            int col = wc + nb * 8 + qt * 2;
            xr[e]   = (xr[e]   + sb[col])   * sigm(acc[e]   + sb[128 + col])   * m;
            xr[e+1] = (xr[e+1] + sb[col+1]) * sigm(acc[e+1] + sb[128 + col+1]) * m;
        }
    }
    CP_WAIT1();
    __syncthreads();

    // ================= stage 2: acc = zn @ w_bp^T; xr *= (P+b)*m =================
#pragma unroll
    for (int e = 0; e < 32; e++) acc[e] = 0.f;
    mm_hhlh(acc, ZH, ZL, WH, ao0, ao1, bo0, bo1);
    __syncthreads();
    prefetch_half(WH, g_w[3][0], t);
    CP_WAIT1();
    __syncthreads();
    mm_hl(acc, ZH, WL, ao0, ao1, bo0, bo1);
    __syncthreads();
    prefetch_half(WL, g_w[3][1], t);
#pragma unroll
    for (int i = 0; i < 4; i++) {
        int row = wr + ((i >> 1) << 4) + ((i & 1) << 3) + quad;
        float m = mk[row];
#pragma unroll
        for (int nb = 0; nb < 4; nb++) {
            int e = ((i >> 1) * 4 + nb) * 4 + (i & 1) * 2;
            int col = wc + nb * 8 + qt * 2;
            xr[e]   *= (acc[e]   + sb[256 + col])   * m;
            xr[e+1] *= (acc[e+1] + sb[256 + col+1]) * m;
        }
    }
    CP_WAIT1();
    __syncthreads();

    // ====== stage 3: acc = zn @ w_bg^T; x = xr*sig; LN partials ======
#pragma unroll
    for (int e = 0; e < 32; e++) acc[e] = 0.f;
    mm_hhlh(acc, ZH, ZL, WH, ao0, ao1, bo0, bo1);
    __syncthreads();
    prefetch_half(WH, g_w[4][0], t);
    CP_WAIT1();
    __syncthreads();
    mm_hl(acc, ZH, WL, ao0, ao1, bo0, bo1);
    __syncthreads();
    prefetch_half(WL, g_w[4][1], t);
#pragma unroll
    for (int i = 0; i < 4; i++) {
        int row = wr + ((i >> 1) << 4) + ((i & 1) << 3) + quad;
        float s = 0.f, s2 = 0.f;
#pragma unroll
        for (int nb = 0; nb < 4; nb++) {
            int e = ((i >> 1) * 4 + nb) * 4 + (i & 1) * 2;
            int col = wc + nb * 8 + qt * 2;
            xr[e]   *= sigm(acc[e]   + sb[384 + col]);
            xr[e+1] *= sigm(acc[e+1] + sb[384 + col+1]);
            s  += xr[e] + xr[e+1];
            s2 += xr[e] * xr[e] + xr[e+1] * xr[e+1];
        }
        s  += __shfl_xor_sync(~0u, s, 1);  s  += __shfl_xor_sync(~0u, s, 2);
        s2 += __shfl_xor_sync(~0u, s2, 1); s2 += __shfl_xor_sync(~0u, s2, 2);
        if (qt == 0) red[row * 4 + wcid] = make_float2(s, s2);
    }
    CP_WAIT1();
    __syncthreads();

    // ================= stage 4: acc = gate = sig(zn @ w_g^T + b_g) =================
#pragma unroll
    for (int e = 0; e < 32; e++) acc[e] = 0.f;
    mm_hhlh(acc, ZH, ZL, WH, ao0, ao1, bo0, bo1);
    __syncthreads();
    prefetch_half(WH, g_w[5][0], t);
    CP_WAIT1();
    __syncthreads();
    mm_hl(acc, ZH, WL, ao0, ao1, bo0, bo1);
    __syncthreads();                         // WL free; all zn reads done
    prefetch_half(WL, g_w[5][1], t);
#pragma unroll
    for (int i = 0; i < 4; i++) {
#pragma unroll
        for (int nb = 0; nb < 4; nb++) {
            int e = ((i >> 1) * 4 + nb) * 4 + (i & 1) * 2;
            int col = wc + nb * 8 + qt * 2;
            acc[e]   = sigm(acc[e]   + sb[512 + col]);
            acc[e+1] = sigm(acc[e+1] + sb[512 + col+1]);
        }
    }
    // LN_out stats from red (written stage 3, visible since then)
    {
        float mu4[4], rs4[4];
#pragma unroll
        for (int i = 0; i < 4; i++) {
            int row = wr + ((i >> 1) << 4) + ((i & 1) << 3) + quad;
            float s = 0.f, s2 = 0.f;
#pragma unroll
            for (int k = 0; k < 4; k++) { float2 p = red[row * 4 + k]; s += p.x; s2 += p.y; }
            mu4[i] = s * (1.f / 128);
            rs4[i] = rsqrtf(fmaxf(s2 * (1.f / 128) - mu4[i] * mu4[i], 0.f) + 1e-5f);
        }
        // overwrite zn smem with xn (hi/lo bf16)
#pragma unroll
        for (int i = 0; i < 4; i++) {
            int row = wr + ((i >> 1) << 4) + ((i & 1) << 3) + quad;
#pragma unroll
            for (int nb = 0; nb < 4; nb++) {
                int e = ((i >> 1) * 4 + nb) * 4 + (i & 1) * 2;
                int col = wc + nb * 8 + qt * 2;
                float v0 = (xr[e]   - mu4[i]) * rs4[i] * sb[768 + col]   + sb[896 + col];
                float v1 = (xr[e+1] - mu4[i]) * rs4[i] * sb[768 + col+1] + sb[896 + col+1];
                __nv_bfloat16 h0 = __float2bfloat16(v0);
                __nv_bfloat16 h1 = __float2bfloat16(v1);
                __nv_bfloat16 l0 = __float2bfloat16(v0 - __bfloat162float(h0));
                __nv_bfloat16 l1 = __float2bfloat16(v1 - __bfloat162float(h1));
                uint32_t hh = ((uint32_t)__bfloat16_as_ushort(h1) << 16) | __bfloat16_as_ushort(h0);
                uint32_t ll = ((uint32_t)__bfloat16_as_ushort(l1) << 16) | __bfloat16_as_ushort(l0);
                uint32_t off = (uint32_t)row * STR + (uint32_t)col * 2u;
                *(uint32_t*)(sm + off) = hh;
                *(uint32_t*)(sm + OFF_ZL + off) = ll;
            }
        }
    }
    CP_WAIT1();                              // Wh(5) done; Wl(5) in flight
    __syncthreads();                         // xn visible CTA-wide

    // ================= stage 5: out = (xn @ w_z^T + b_z) * gate =================
#pragma unroll
    for (int e = 0; e < 32; e++) xr[e] = 0.f;
    mm_hhlh(xr, ZH, ZL, WH, ao0, ao1, bo0, bo1);
    CP_WAIT0();                              // Wl(5) done (per-thread)
    __syncthreads();                         // ... and visible CTA-wide
    mm_hl(xr, ZH, WL, ao0, ao1, bo0, bo1);
#pragma unroll
    for (int i = 0; i < 4; i++) {
        int row = wr + ((i >> 1) << 4) + ((i & 1) << 3) + quad;
        float* orow = out + (row0 + row) * 128;
#pragma unroll
        for (int nb = 0; nb < 4; nb++) {
            int e = ((i >> 1) * 4 + nb) * 4 + (i & 1) * 2;
            int col = wc + nb * 8 + qt * 2;
            float2 o;
            o.x = (xr[e]   + sb[640 + col])   * acc[e];
            o.y = (xr[e+1] + sb[640 + col+1]) * acc[e+1];
            *(float2*)(orow + col) = o;
        }
    }
}

extern "C" void kernel_launch(void* const* d_in, const int* in_sizes, int n_in,
                              void* d_out, int out_size) {
    const float* z        = (const float*)d_in[0];
    const float* mask     = (const float*)d_in[1];
    const float* w_ap     = (const float*)d_in[2];
    const float* b_ap     = (const float*)d_in[3];
    const float* w_bp     = (const float*)d_in[4];
    const float* b_bp     = (const float*)d_in[5];
    const float* w_ag     = (const float*)d_in[6];
    const float* b_ag     = (const float*)d_in[7];
    const float* w_bg     = (const float*)d_in[8];
    const float* b_bg     = (const float*)d_in[9];
    const float* w_g      = (const float*)d_in[10];
    const float* b_g      = (const float*)d_in[11];
    const float* w_z      = (const float*)d_in[12];
    const float* b_z      = (const float*)d_in[13];
    const float* ln_in_w  = (const float*)d_in[14];
    const float* ln_in_b  = (const float*)d_in[15];
    const float* ln_out_w = (const float*)d_in[16];
    const float* ln_out_b = (const float*)d_in[17];
    float* out = (float*)d_out;

    const int rows = in_sizes[1];      // B*N*N
    const int nblocks = rows / 64;     // 2304

    static int configured = 0;
    if (!configured) {
        cudaFuncSetAttribute(tmu_kernel, cudaFuncAttributeMaxDynamicSharedMemorySize, SMEM_BYTES);
        configured = 1;
    }

    // stage order in g_w: 0=w_ap 1=w_ag 2=w_bp 3=w_bg 4=w_g 5=w_z
    kPrep<<<6, 512>>>(w_ap, w_ag, w_bp, w_bg, w_g, w_z);
    tmu_kernel<<<nblocks, NT, SMEM_BYTES>>>(z, mask,
                                            b_ap, b_ag, b_bp, b_bg, b_g, b_z,
                                            ln_in_w, ln_in_b, ln_out_w, ln_out_b,
                                            out);
}

// round 6
// speedup vs baseline: 2.4086x; 1.1102x over previous
#include <cuda_runtime.h>
#include <cuda_fp16.h>
#include <stdint.h>

// TriangleMultiplicativeUpdate, fused, mma.sync m16n8k16 **fp16** with 2-term
// hi/lo split (fp32 accum): A*B ~= Ah*Bh + Ah*Bl (fp16 mantissa makes the
// dropped Al*Bh term ~2.8e-4 rel). Stage 5 (w_z) keeps a 3rd pass (Al*Bh with
// xn-lo) as cheap insurance. 33% fewer tensor instructions than the bf16
// 3-term kernel; zn-lo tile eliminated.

#define NT 256
#define STR 272u   // smem row stride in bytes (136 fp16): conflict-free ldmatrix

#define OFF_ZH  0u            // zn/xn hi: 64 x 272
#define OFF_XL  17408u        // xn lo (stage-5 correction only)
#define OFF_WH  34816u        // weight hi: 128 x 272
#define OFF_WL  69632u        // weight lo
#define OFF_SB  104448u       // 8 x 128 floats (biases, ln_out w/b)
#define OFF_MK  108544u       // 64 floats (mask)
#define OFF_RED 108800u       // 64 x 4 float2 (LN_out partials)
#define SMEM_BYTES 110848

// weights as fp16 hi/lo, linear [n][k]; 0=w_ap 1=w_ag 2=w_bp 3=w_bg 4=w_g 5=w_z
__device__ __align__(16) __half g_w[6][2][128 * 128];

__device__ __forceinline__ uint32_t s2u(const void* p) {
    uint32_t a;
    asm("{ .reg .u64 t; cvta.to.shared.u64 t, %1; cvt.u32.u64 %0, t; }" : "=r"(a) : "l"(p));
    return a;
}

#define LDSM4(r, a) \
    asm volatile("ldmatrix.sync.aligned.m8n8.x4.shared.b16 {%0,%1,%2,%3}, [%4];" \
        : "=r"((r)[0]), "=r"((r)[1]), "=r"((r)[2]), "=r"((r)[3]) : "r"(a))

#define MMAOP(d, a, b0, b1) \
    asm volatile("mma.sync.aligned.m16n8k16.row.col.f32.f16.f16.f32 " \
        "{%0,%1,%2,%3}, {%4,%5,%6,%7}, {%8,%9}, {%0,%1,%2,%3};" \
        : "+f"((d)[0]), "+f"((d)[1]), "+f"((d)[2]), "+f"((d)[3]) \
        : "r"((a)[0]), "r"((a)[1]), "r"((a)[2]), "r"((a)[3]), "r"(b0), "r"(b1))

#define CPA16(dst, src) \
    asm volatile("cp.async.cg.shared.global [%0], [%1], 16;" :: "r"(dst), "l"(src))
#define CP_COMMIT() asm volatile("cp.async.commit_group;" ::: "memory")
#define CP_WAIT0()  asm volatile("cp.async.wait_group 0;" ::: "memory")
#define CP_WAIT1()  asm volatile("cp.async.wait_group 1;" ::: "memory")

__device__ __forceinline__ float sigm(float x) { return 1.0f / (1.0f + __expf(-x)); }

// one pass: acc += Atile @ Wslot^T  (64x32 rows per warp-row, 8 mma per k-step)
__device__ __forceinline__ void mm2(float* acc, uint32_t atile, uint32_t wslot,
                                    uint32_t ao0, uint32_t ao1,
                                    uint32_t bo0, uint32_t bo1) {
#pragma unroll
    for (int k = 0; k < 8; k++) {
        uint32_t ko = (uint32_t)k * 32u;
        uint32_t A0[4], A1[4], B0[4], B1[4];
        LDSM4(A0, atile + ao0 + ko); LDSM4(A1, atile + ao1 + ko);
        LDSM4(B0, wslot + bo0 + ko); LDSM4(B1, wslot + bo1 + ko);
        MMAOP(acc + 0,  A0, B0[0], B0[1]); MMAOP(acc + 4,  A0, B0[2], B0[3]);
        MMAOP(acc + 8,  A0, B1[0], B1[1]); MMAOP(acc + 12, A0, B1[2], B1[3]);
        MMAOP(acc + 16, A1, B0[0], B0[1]); MMAOP(acc + 20, A1, B0[2], B0[3]);
        MMAOP(acc + 24, A1, B1[0], B1[1]); MMAOP(acc + 28, A1, B1[2], B1[3]);
    }
}

// async-copy one weight matrix half (32KB) into a padded smem slot; one group
__device__ __forceinline__ void prefetch_half(uint32_t dst, const __half* src, int t) {
    const char* s = (const char*)src;
#pragma unroll
    for (int i = 0; i < 8; i++) {
        int cid = t + i * NT;                  // 2048 16B chunks
        uint32_t d = (uint32_t)(cid >> 4) * STR + (uint32_t)(cid & 15) * 16u;
        CPA16(dst + d, s + (size_t)cid * 16);
    }
    CP_COMMIT();
}

__global__ void kPrep(const float* __restrict__ w0, const float* __restrict__ w1,
                      const float* __restrict__ w2, const float* __restrict__ w3,
                      const float* __restrict__ w4, const float* __restrict__ w5) {
    const float* w;
    switch (blockIdx.x) {
        case 0: w = w0; break; case 1: w = w1; break; case 2: w = w2; break;
        case 3: w = w3; break; case 4: w = w4; break; default: w = w5; break;
    }
    __half* h = g_w[blockIdx.x][0];
    __half* l = g_w[blockIdx.x][1];
    for (int i = threadIdx.x; i < 128 * 128; i += blockDim.x) {
        float v = __ldg(w + i);
        __half hh = __float2half(v);
        h[i] = hh;
        l[i] = __float2half(v - __half2float(hh));
    }
}

__global__ void __launch_bounds__(NT, 2)
tmu_kernel(const float* __restrict__ z, const float* __restrict__ mask,
           const float* __restrict__ b_ap, const float* __restrict__ b_ag,
           const float* __restrict__ b_bp, const float* __restrict__ b_bg,
           const float* __restrict__ b_g,  const float* __restrict__ b_z,
           const float* __restrict__ ln_in_w,  const float* __restrict__ ln_in_b,
           const float* __restrict__ ln_out_w, const float* __restrict__ ln_out_b,
           float* __restrict__ out) {
    extern __shared__ char sm[];
    const uint32_t smb = s2u(sm);
    const int t = threadIdx.x;
    const int w = t >> 5, lid = t & 31;
    const int quad = lid >> 2, qt = lid & 3;
    const int wr = (w & 1) * 32, wc = (w >> 1) * 32;
    const int wcid = w >> 1;
    const size_t row0 = (size_t)blockIdx.x * 64;

    float* sb = (float*)(sm + OFF_SB);
    float* mk = (float*)(sm + OFF_MK);
    float2* red = (float2*)(sm + OFF_RED);

    const uint32_t ZH = smb + OFF_ZH, XL = smb + OFF_XL;
    const uint32_t WH = smb + OFF_WH, WL = smb + OFF_WL;

    const uint32_t ao0 = (uint32_t)(wr + (lid & 15)) * STR + (uint32_t)(lid >> 4) * 16u;
    const uint32_t ao1 = ao0 + 16u * STR;
    const uint32_t bo0 = (uint32_t)(wc + (lid & 7) + ((lid >> 4) << 3)) * STR +
                         (uint32_t)((lid >> 3) & 1) * 16u;
    const uint32_t bo1 = bo0 + 16u * STR;

    // bootstrap: start both halves of weight 0 (two cp groups in flight)
    prefetch_half(WH, g_w[0][0], t);
    prefetch_half(WL, g_w[0][1], t);

    if (t < 128) {
        sb[t] = __ldg(b_ap + t);           sb[128 + t] = __ldg(b_ag + t);
        sb[256 + t] = __ldg(b_bp + t);     sb[384 + t] = __ldg(b_bg + t);
        sb[512 + t] = __ldg(b_g + t);      sb[640 + t] = __ldg(b_z + t);
        sb[768 + t] = __ldg(ln_out_w + t); sb[896 + t] = __ldg(ln_out_b + t);
    }

    // ---- LN_in: 4 threads/row over 64 rows; write zn (fp16 hi only) ----
    {
        const int r = t >> 2, q = t & 3;
        const float* zr = z + (row0 + r) * 128 + q * 32;
        float v[32], s = 0.f, s2 = 0.f;
#pragma unroll
        for (int i = 0; i < 8; i++) {
            float4 f = __ldg((const float4*)(zr + 4 * i));
            v[4*i] = f.x; v[4*i+1] = f.y; v[4*i+2] = f.z; v[4*i+3] = f.w;
            s += f.x + f.y + f.z + f.w;
            s2 += f.x*f.x + f.y*f.y + f.z*f.z + f.w*f.w;
        }
        s  += __shfl_xor_sync(~0u, s, 1);  s  += __shfl_xor_sync(~0u, s, 2);
        s2 += __shfl_xor_sync(~0u, s2, 1); s2 += __shfl_xor_sync(~0u, s2, 2);
        float mu = s * (1.f / 128);
        float rstd = rsqrtf(fmaxf(s2 * (1.f / 128) - mu * mu, 0.f) + 1e-5f);
#pragma unroll
        for (int j = 0; j < 4; j++) {
            union { uint4 u; __half b[8]; } H;
#pragma unroll
            for (int i = 0; i < 8; i++) {
                int c = q * 32 + j * 8 + i;
                float f = (v[j*8+i] - mu) * rstd * __ldg(ln_in_w + c) + __ldg(ln_in_b + c);
                H.b[i] = __float2half(f);
            }
            uint32_t off = (uint32_t)r * STR + (uint32_t)(q * 4 + j) * 16u;
            *(uint4*)(sm + off) = H.u;
        }
        if (q == 0) mk[r] = __ldg(mask + row0 + r);
    }

    float xr[32], acc[32];

    // entry invariant per stage s: W_hi(s) landed CTA-wide; W_lo(s) = the one
    // outstanding cp group (or landed).

    CP_WAIT1();            // Wh(0) done; Wl(0) in flight
    __syncthreads();

    // ================= stage 0: xr = zn @ w_ap^T =================
#pragma unroll
    for (int e = 0; e < 32; e++) xr[e] = 0.f;
    mm2(xr, ZH, WH, ao0, ao1, bo0, bo1);
    __syncthreads();                         // WH free
    prefetch_half(WH, g_w[1][0], t);         // Wh(1) ->
    CP_WAIT1();                              // Wl(0) done
    __syncthreads();
    mm2(xr, ZH, WL, ao0, ao1, bo0, bo1);
    __syncthreads();                         // WL free
    prefetch_half(WL, g_w[1][1], t);         // Wl(1) ->
    CP_WAIT1();                              // Wh(1) done
    __syncthreads();

    // ================= stage 1: acc = zn @ w_ag^T; xr = a =================
#pragma unroll
    for (int e = 0; e < 32; e++) acc[e] = 0.f;
    mm2(acc, ZH, WH, ao0, ao1, bo0, bo1);
    __syncthreads();
    prefetch_half(WH, g_w[2][0], t);
    CP_WAIT1();
    __syncthreads();
    mm2(acc, ZH, WL, ao0, ao1, bo0, bo1);
    __syncthreads();
    prefetch_half(WL, g_w[2][1], t);
#pragma unroll
    for (int i = 0; i < 4; i++) {
        int row = wr + ((i >> 1) << 4) + ((i & 1) << 3) + quad;
        float m = mk[row];
#pragma unroll
        for (int nb = 0; nb < 4; nb++) {
            int e = ((i >> 1) * 4 + nb) * 4 + (i & 1) * 2;
            int col = wc + nb * 8 + qt * 2;
            xr[e]   = (xr[e]   + sb[col])   * sigm(acc[e]   + sb[128 + col])   * m;
            xr[e+1] = (xr[e+1] + sb[col+1]) * sigm(acc[e+1] + sb[128 + col+1]) * m;
        }
    }
    CP_WAIT1();
    __syncthreads();

    // ================= stage 2: acc = zn @ w_bp^T; xr *= (P+b)*m =================
#pragma unroll
    for (int e = 0; e < 32; e++) acc[e] = 0.f;
    mm2(acc, ZH, WH, ao0, ao1, bo0, bo1);
    __syncthreads();
    prefetch_half(WH, g_w[3][0], t);
    CP_WAIT1();
    __syncthreads();
    mm2(acc, ZH, WL, ao0, ao1, bo0, bo1);
    __syncthreads();
    prefetch_half(WL, g_w[3][1], t);
#pragma unroll
    for (int i = 0; i < 4; i++) {
        int row = wr + ((i >> 1) << 4) + ((i & 1) << 3) + quad;
        float m = mk[row];
#pragma unroll
        for (int nb = 0; nb < 4; nb++) {
            int e = ((i >> 1) * 4 + nb) * 4 + (i & 1) * 2;
            int col = wc + nb * 8 + qt * 2;
            xr[e]   *= (acc[e]   + sb[256 + col])   * m;
            xr[e+1] *= (acc[e+1] + sb[256 + col+1]) * m;
        }
    }
    CP_WAIT1();
    __syncthreads();

    // ====== stage 3: acc = zn @ w_bg^T; x = xr*sig; LN partials ======
#pragma unroll
    for (int e = 0; e < 32; e++) acc[e] = 0.f;
    mm2(acc, ZH, WH, ao0, ao1, bo0, bo1);
    __syncthreads();
    prefetch_half(WH, g_w[4][0], t);
    CP_WAIT1();
    __syncthreads();
    mm2(acc, ZH, WL, ao0, ao1, bo0, bo1);
    __syncthreads();
    prefetch_half(WL, g_w[4][1], t);
#pragma unroll
    for (int i = 0; i < 4; i++) {
        int row = wr + ((i >> 1) << 4) + ((i & 1) << 3) + quad;
        float s = 0.f, s2 = 0.f;
#pragma unroll
        for (int nb = 0; nb < 4; nb++) {
            int e = ((i >> 1) * 4 + nb) * 4 + (i & 1) * 2;
            int col = wc + nb * 8 + qt * 2;
            xr[e]   *= sigm(acc[e]   + sb[384 + col]);
            xr[e+1] *= sigm(acc[e+1] + sb[384 + col+1]);
            s  += xr[e] + xr[e+1];
            s2 += xr[e] * xr[e] + xr[e+1] * xr[e+1];
        }
        s  += __shfl_xor_sync(~0u, s, 1);  s  += __shfl_xor_sync(~0u, s, 2);
        s2 += __shfl_xor_sync(~0u, s2, 1); s2 += __shfl_xor_sync(~0u, s2, 2);
        if (qt == 0) red[row * 4 + wcid] = make_float2(s, s2);
    }
    CP_WAIT1();
    __syncthreads();

    // ================= stage 4: acc = gate = sig(zn @ w_g^T + b_g) =================
#pragma unroll
    for (int e = 0; e < 32; e++) acc[e] = 0.f;
    mm2(acc, ZH, WH, ao0, ao1, bo0, bo1);
    __syncthreads();
    prefetch_half(WH, g_w[5][0], t);
    CP_WAIT1();
    __syncthreads();
    mm2(acc, ZH, WL, ao0, ao1, bo0, bo1);
    __syncthreads();                         // WL free; all zn reads done
    prefetch_half(WL, g_w[5][1], t);
#pragma unroll
    for (int i = 0; i < 4; i++) {
#pragma unroll
        for (int nb = 0; nb < 4; nb++) {
            int e = ((i >> 1) * 4 + nb) * 4 + (i & 1) * 2;
            int col = wc + nb * 8 + qt * 2;
            acc[e]   = sigm(acc[e]   + sb[512 + col]);
            acc[e+1] = sigm(acc[e+1] + sb[512 + col+1]);
        }
    }
    // LN_out stats from red (written stage 3, visible since then)
    {
        float mu4[4], rs4[4];
#pragma unroll
        for (int i = 0; i < 4; i++) {
            int row = wr + ((i >> 1) << 4) + ((i & 1) << 3) + quad;
            float s = 0.f, s2 = 0.f;
#pragma unroll
            for (int k = 0; k < 4; k++) { float2 p = red[row * 4 + k]; s += p.x; s2 += p.y; }
            mu4[i] = s * (1.f / 128);
            rs4[i] = rsqrtf(fmaxf(s2 * (1.f / 128) - mu4[i] * mu4[i], 0.f) + 1e-5f);
        }
        // overwrite zn smem with xn hi; write xn lo to XL (stage-5 3rd pass)
#pragma unroll
        for (int i = 0; i < 4; i++) {
            int row = wr + ((i >> 1) << 4) + ((i & 1) << 3) + quad;
#pragma unroll
            for (int nb = 0; nb < 4; nb++) {
                int e = ((i >> 1) * 4 + nb) * 4 + (i & 1) * 2;
                int col = wc + nb * 8 + qt * 2;
                float v0 = (xr[e]   - mu4[i]) * rs4[i] * sb[768 + col]   + sb[896 + col];
                float v1 = (xr[e+1] - mu4[i]) * rs4[i] * sb[768 + col+1] + sb[896 + col+1];
                __half h0 = __float2half(v0);
                __half h1 = __float2half(v1);
                __half l0 = __float2half(v0 - __half2float(h0));
                __half l1 = __float2half(v1 - __half2float(h1));
                uint32_t hh = ((uint32_t)__half_as_ushort(h1) << 16) | __half_as_ushort(h0);
                uint32_t ll = ((uint32_t)__half_as_ushort(l1) << 16) | __half_as_ushort(l0);
                uint32_t off = (uint32_t)row * STR + (uint32_t)col * 2u;
                *(uint32_t*)(sm + off) = hh;
                *(uint32_t*)(sm + OFF_XL + off) = ll;
            }
        }
    }
    CP_WAIT1();                              // Wh(5) done; Wl(5) in flight
    __syncthreads();                         // xn visible CTA-wide

    // ====== stage 5: out = (xn @ w_z^T + b_z) * gate  (3 passes) ======
#pragma unroll
    for (int e = 0; e < 32; e++) xr[e] = 0.f;
    mm2(xr, ZH, WH, ao0, ao1, bo0, bo1);     // Ah*Bh
    mm2(xr, XL, WH, ao0, ao1, bo0, bo1);     // Al*Bh (xn-lo correction)
    CP_WAIT0();                              // Wl(5) done (per-thread)
    __syncthreads();                         // ... and visible CTA-wide
    mm2(xr, ZH, WL, ao0, ao1, bo0, bo1);     // Ah*Bl
#pragma unroll
    for (int i = 0; i < 4; i++) {
        int row = wr + ((i >> 1) << 4) + ((i & 1) << 3) + quad;
        float* orow = out + (row0 + row) * 128;
#pragma unroll
        for (int nb = 0; nb < 4; nb++) {
            int e = ((i >> 1) * 4 + nb) * 4 + (i & 1) * 2;
            int col = wc + nb * 8 + qt * 2;
            float2 o;
            o.x = (xr[e]   + sb[640 + col])   * acc[e];
            o.y = (xr[e+1] + sb[640 + col+1]) * acc[e+1];
            *(float2*)(orow + col) = o;
        }
    }
}

extern "C" void kernel_launch(void* const* d_in, const int* in_sizes, int n_in,
                              void* d_out, int out_size) {
    const float* z        = (const float*)d_in[0];
    const float* mask     = (const float*)d_in[1];
    const float* w_ap     = (const float*)d_in[2];
    const float* b_ap     = (const float*)d_in[3];
    const float* w_bp     = (const float*)d_in[4];
    const float* b_bp     = (const float*)d_in[5];
    const float* w_ag     = (const float*)d_in[6];
    const float* b_ag     = (const float*)d_in[7];
    const float* w_bg     = (const float*)d_in[8];
    const float* b_bg     = (const float*)d_in[9];
    const float* w_g      = (const float*)d_in[10];
    const float* b_g      = (const float*)d_in[11];
    const float* w_z      = (const float*)d_in[12];
    const float* b_z      = (const float*)d_in[13];
    const float* ln_in_w  = (const float*)d_in[14];
    const float* ln_in_b  = (const float*)d_in[15];
    const float* ln_out_w = (const float*)d_in[16];
    const float* ln_out_b = (const float*)d_in[17];
    float* out = (float*)d_out;

    const int rows = in_sizes[1];      // B*N*N
    const int nblocks = rows / 64;     // 2304

    static int configured = 0;
    if (!configured) {
        cudaFuncSetAttribute(tmu_kernel, cudaFuncAttributeMaxDynamicSharedMemorySize, SMEM_BYTES);
        configured = 1;
    }

    // stage order in g_w: 0=w_ap 1=w_ag 2=w_bp 3=w_bg 4=w_g 5=w_z
    kPrep<<<6, 512>>>(w_ap, w_ag, w_bp, w_bg, w_g, w_z);
    tmu_kernel<<<nblocks, NT, SMEM_BYTES>>>(z, mask,
                                            b_ap, b_ag, b_bp, b_bg, b_g, b_z,
                                            ln_in_w, ln_in_b, ln_out_w, ln_out_b,
                                            out);
}

// round 7
// speedup vs baseline: 2.4089x; 1.0001x over previous
#include <cuda_runtime.h>
#include <cuda_fp16.h>
#include <stdint.h>

// TriangleMultiplicativeUpdate, fused, mma.sync m16n8k16 **fp16** with 2-term
// hi/lo split (fp32 accum): A*B ~= Ah*Bh + Ah*Bl (fp16 mantissa makes the
// dropped Al*Bh term ~2.8e-4 rel). Stage 5 (w_z) keeps a 3rd pass (Al*Bh with
// xn-lo) as cheap insurance. 33% fewer tensor instructions than the bf16
// 3-term kernel; zn-lo tile eliminated.

#define NT 256
#define STR 272u   // smem row stride in bytes (136 fp16): conflict-free ldmatrix

#define OFF_ZH  0u            // zn/xn hi: 64 x 272
#define OFF_XL  17408u        // xn lo (stage-5 correction only)
#define OFF_WH  34816u        // weight hi: 128 x 272
#define OFF_WL  69632u        // weight lo
#define OFF_SB  104448u       // 8 x 128 floats (biases, ln_out w/b)
#define OFF_MK  108544u       // 64 floats (mask)
#define OFF_RED 108800u       // 64 x 4 float2 (LN_out partials)
#define SMEM_BYTES 110848

// weights as fp16 hi/lo, linear [n][k]; 0=w_ap 1=w_ag 2=w_bp 3=w_bg 4=w_g 5=w_z
__device__ __align__(16) __half g_w[6][2][128 * 128];

__device__ __forceinline__ uint32_t s2u(const void* p) {
    uint32_t a;
    asm("{ .reg .u64 t; cvta.to.shared.u64 t, %1; cvt.u32.u64 %0, t; }" : "=r"(a) : "l"(p));
    return a;
}

#define LDSM4(r, a) \
    asm volatile("ldmatrix.sync.aligned.m8n8.x4.shared.b16 {%0,%1,%2,%3}, [%4];" \
        : "=r"((r)[0]), "=r"((r)[1]), "=r"((r)[2]), "=r"((r)[3]) : "r"(a))

#define MMAOP(d, a, b0, b1) \
    asm volatile("mma.sync.aligned.m16n8k16.row.col.f32.f16.f16.f32 " \
        "{%0,%1,%2,%3}, {%4,%5,%6,%7}, {%8,%9}, {%0,%1,%2,%3};" \
        : "+f"((d)[0]), "+f"((d)[1]), "+f"((d)[2]), "+f"((d)[3]) \
        : "r"((a)[0]), "r"((a)[1]), "r"((a)[2]), "r"((a)[3]), "r"(b0), "r"(b1))

#define CPA16(dst, src) \
    asm volatile("cp.async.cg.shared.global [%0], [%1], 16;" :: "r"(dst), "l"(src))
#define CP_COMMIT() asm volatile("cp.async.commit_group;" ::: "memory")
#define CP_WAIT0()  asm volatile("cp.async.wait_group 0;" ::: "memory")
#define CP_WAIT1()  asm volatile("cp.async.wait_group 1;" ::: "memory")

__device__ __forceinline__ float sigm(float x) { return 1.0f / (1.0f + __expf(-x)); }

// one pass: acc += Atile @ Wslot^T  (64x32 rows per warp-row, 8 mma per k-step)
__device__ __forceinline__ void mm2(float* acc, uint32_t atile, uint32_t wslot,
                                    uint32_t ao0, uint32_t ao1,
                                    uint32_t bo0, uint32_t bo1) {
#pragma unroll
    for (int k = 0; k < 8; k++) {
        uint32_t ko = (uint32_t)k * 32u;
        uint32_t A0[4], A1[4], B0[4], B1[4];
        LDSM4(A0, atile + ao0 + ko); LDSM4(A1, atile + ao1 + ko);
        LDSM4(B0, wslot + bo0 + ko); LDSM4(B1, wslot + bo1 + ko);
        MMAOP(acc + 0,  A0, B0[0], B0[1]); MMAOP(acc + 4,  A0, B0[2], B0[3]);
        MMAOP(acc + 8,  A0, B1[0], B1[1]); MMAOP(acc + 12, A0, B1[2], B1[3]);
        MMAOP(acc + 16, A1, B0[0], B0[1]); MMAOP(acc + 20, A1, B0[2], B0[3]);
        MMAOP(acc + 24, A1, B1[0], B1[1]); MMAOP(acc + 28, A1, B1[2], B1[3]);
    }
}

// async-copy one weight matrix half (32KB) into a padded smem slot; one group
__device__ __forceinline__ void prefetch_half(uint32_t dst, const __half* src, int t) {
    const char* s = (const char*)src;
#pragma unroll
    for (int i = 0; i < 8; i++) {
        int cid = t + i * NT;                  // 2048 16B chunks
        uint32_t d = (uint32_t)(cid >> 4) * STR + (uint32_t)(cid & 15) * 16u;
        CPA16(dst + d, s + (size_t)cid * 16);
    }
    CP_COMMIT();
}

__global__ void kPrep(const float* __restrict__ w0, const float* __restrict__ w1,
                      const float* __restrict__ w2, const float* __restrict__ w3,
                      const float* __restrict__ w4, const float* __restrict__ w5) {
    const float* w;
    switch (blockIdx.x) {
        case 0: w = w0; break; case 1: w = w1; break; case 2: w = w2; break;
        case 3: w = w3; break; case 4: w = w4; break; default: w = w5; break;
    }
    __half* h = g_w[blockIdx.x][0];
    __half* l = g_w[blockIdx.x][1];
    for (int i = threadIdx.x; i < 128 * 128; i += blockDim.x) {
        float v = __ldg(w + i);
        __half hh = __float2half(v);
        h[i] = hh;
        l[i] = __float2half(v - __half2float(hh));
    }
}

__global__ void __launch_bounds__(NT, 2)
tmu_kernel(const float* __restrict__ z, const float* __restrict__ mask,
           const float* __restrict__ b_ap, const float* __restrict__ b_ag,
           const float* __restrict__ b_bp, const float* __restrict__ b_bg,
           const float* __restrict__ b_g,  const float* __restrict__ b_z,
           const float* __restrict__ ln_in_w,  const float* __restrict__ ln_in_b,
           const float* __restrict__ ln_out_w, const float* __restrict__ ln_out_b,
           float* __restrict__ out) {
    extern __shared__ char sm[];
    const uint32_t smb = s2u(sm);
    const int t = threadIdx.x;
    const int w = t >> 5, lid = t & 31;
    const int quad = lid >> 2, qt = lid & 3;
    const int wr = (w & 1) * 32, wc = (w >> 1) * 32;
    const int wcid = w >> 1;
    const size_t row0 = (size_t)blockIdx.x * 64;

    float* sb = (float*)(sm + OFF_SB);
    float* mk = (float*)(sm + OFF_MK);
    float2* red = (float2*)(sm + OFF_RED);

    const uint32_t ZH = smb + OFF_ZH, XL = smb + OFF_XL;
    const uint32_t WH = smb + OFF_WH, WL = smb + OFF_WL;

    const uint32_t ao0 = (uint32_t)(wr + (lid & 15)) * STR + (uint32_t)(lid >> 4) * 16u;
    const uint32_t ao1 = ao0 + 16u * STR;
    const uint32_t bo0 = (uint32_t)(wc + (lid & 7) + ((lid >> 4) << 3)) * STR +
                         (uint32_t)((lid >> 3) & 1) * 16u;
    const uint32_t bo1 = bo0 + 16u * STR;

    // bootstrap: start both halves of weight 0 (two cp groups in flight)
    prefetch_half(WH, g_w[0][0], t);
    prefetch_half(WL, g_w[0][1], t);

    if (t < 128) {
        sb[t] = __ldg(b_ap + t);           sb[128 + t] = __ldg(b_ag + t);
        sb[256 + t] = __ldg(b_bp + t);     sb[384 + t] = __ldg(b_bg + t);
        sb[512 + t] = __ldg(b_g + t);      sb[640 + t] = __ldg(b_z + t);
        sb[768 + t] = __ldg(ln_out_w + t); sb[896 + t] = __ldg(ln_out_b + t);
    }

    // ---- LN_in: 4 threads/row over 64 rows; write zn (fp16 hi only) ----
    {
        const int r = t >> 2, q = t & 3;
        const float* zr = z + (row0 + r) * 128 + q * 32;
        float v[32], s = 0.f, s2 = 0.f;
#pragma unroll
        for (int i = 0; i < 8; i++) {
            float4 f = __ldg((const float4*)(zr + 4 * i));
            v[4*i] = f.x; v[4*i+1] = f.y; v[4*i+2] = f.z; v[4*i+3] = f.w;
            s += f.x + f.y + f.z + f.w;
            s2 += f.x*f.x + f.y*f.y + f.z*f.z + f.w*f.w;
        }
        s  += __shfl_xor_sync(~0u, s, 1);  s  += __shfl_xor_sync(~0u, s, 2);
        s2 += __shfl_xor_sync(~0u, s2, 1); s2 += __shfl_xor_sync(~0u, s2, 2);
        float mu = s * (1.f / 128);
        float rstd = rsqrtf(fmaxf(s2 * (1.f / 128) - mu * mu, 0.f) + 1e-5f);
#pragma unroll
        for (int j = 0; j < 4; j++) {
            union { uint4 u; __half b[8]; } H;
#pragma unroll
            for (int i = 0; i < 8; i++) {
                int c = q * 32 + j * 8 + i;
                float f = (v[j*8+i] - mu) * rstd * __ldg(ln_in_w + c) + __ldg(ln_in_b + c);
                H.b[i] = __float2half(f);
            }
            uint32_t off = (uint32_t)r * STR + (uint32_t)(q * 4 + j) * 16u;
            *(uint4*)(sm + off) = H.u;
        }
        if (q == 0) mk[r] = __ldg(mask + row0 + r);
    }

    float xr[32], acc[32];

    // entry invariant per stage s: W_hi(s) landed CTA-wide; W_lo(s) = the one
    // outstanding cp group (or landed).

    CP_WAIT1();            // Wh(0) done; Wl(0) in flight
    __syncthreads();

    // ================= stage 0: xr = zn @ w_ap^T =================
#pragma unroll
    for (int e = 0; e < 32; e++) xr[e] = 0.f;
    mm2(xr, ZH, WH, ao0, ao1, bo0, bo1);
    __syncthreads();                         // WH free
    prefetch_half(WH, g_w[1][0], t);         // Wh(1) ->
    CP_WAIT1();                              // Wl(0) done
    __syncthreads();
    mm2(xr, ZH, WL, ao0, ao1, bo0, bo1);
    __syncthreads();                         // WL free
    prefetch_half(WL, g_w[1][1], t);         // Wl(1) ->
    CP_WAIT1();                              // Wh(1) done
    __syncthreads();

    // ================= stage 1: acc = zn @ w_ag^T; xr = a =================
#pragma unroll
    for (int e = 0; e < 32; e++) acc[e] = 0.f;
    mm2(acc, ZH, WH, ao0, ao1, bo0, bo1);
    __syncthreads();
    prefetch_half(WH, g_w[2][0], t);
    CP_WAIT1();
    __syncthreads();
    mm2(acc, ZH, WL, ao0, ao1, bo0, bo1);
    __syncthreads();
    prefetch_half(WL, g_w[2][1], t);
#pragma unroll
    for (int i = 0; i < 4; i++) {
        int row = wr + ((i >> 1) << 4) + ((i & 1) << 3) + quad;
        float m = mk[row];
#pragma unroll
        for (int nb = 0; nb < 4; nb++) {
            int e = ((i >> 1) * 4 + nb) * 4 + (i & 1) * 2;
            int col = wc + nb * 8 + qt * 2;
            xr[e]   = (xr[e]   + sb[col])   * sigm(acc[e]   + sb[128 + col])   * m;
            xr[e+1] = (xr[e+1] + sb[col+1]) * sigm(acc[e+1] + sb[128 + col+1]) * m;
        }
    }
    CP_WAIT1();
    __syncthreads();

    // ================= stage 2: acc = zn @ w_bp^T; xr *= (P+b)*m =================
#pragma unroll
    for (int e = 0; e < 32; e++) acc[e] = 0.f;
    mm2(acc, ZH, WH, ao0, ao1, bo0, bo1);
    __syncthreads();
    prefetch_half(WH, g_w[3][0], t);
    CP_WAIT1();
    __syncthreads();
    mm2(acc, ZH, WL, ao0, ao1, bo0, bo1);
    __syncthreads();
    prefetch_half(WL, g_w[3][1], t);
#pragma unroll
    for (int i = 0; i < 4; i++) {
        int row = wr + ((i >> 1) << 4) + ((i & 1) << 3) + quad;
        float m = mk[row];
#pragma unroll
        for (int nb = 0; nb < 4; nb++) {
            int e = ((i >> 1) * 4 + nb) * 4 + (i & 1) * 2;
            int col = wc + nb * 8 + qt * 2;
            xr[e]   *= (acc[e]   + sb[256 + col])   * m;
            xr[e+1] *= (acc[e+1] + sb[256 + col+1]) * m;
        }
    }
    CP_WAIT1();
    __syncthreads();

    // ====== stage 3: acc = zn @ w_bg^T; x = xr*sig; LN partials ======
#pragma unroll
    for (int e = 0; e < 32; e++) acc[e] = 0.f;
    mm2(acc, ZH, WH, ao0, ao1, bo0, bo1);
    __syncthreads();
    prefetch_half(WH, g_w[4][0], t);
    CP_WAIT1();
    __syncthreads();
    mm2(acc, ZH, WL, ao0, ao1, bo0, bo1);
    __syncthreads();
    prefetch_half(WL, g_w[4][1], t);
#pragma unroll
    for (int i = 0; i < 4; i++) {
        int row = wr + ((i >> 1) << 4) + ((i & 1) << 3) + quad;
        float s = 0.f, s2 = 0.f;
#pragma unroll
        for (int nb = 0; nb < 4; nb++) {
            int e = ((i >> 1) * 4 + nb) * 4 + (i & 1) * 2;
            int col = wc + nb * 8 + qt * 2;
            xr[e]   *= sigm(acc[e]   + sb[384 + col]);
            xr[e+1] *= sigm(acc[e+1] + sb[384 + col+1]);
            s  += xr[e] + xr[e+1];
            s2 += xr[e] * xr[e] + xr[e+1] * xr[e+1];
        }
        s  += __shfl_xor_sync(~0u, s, 1);  s  += __shfl_xor_sync(~0u, s, 2);
        s2 += __shfl_xor_sync(~0u, s2, 1); s2 += __shfl_xor_sync(~0u, s2, 2);
        if (qt == 0) red[row * 4 + wcid] = make_float2(s, s2);
    }
    CP_WAIT1();
    __syncthreads();

    // ================= stage 4: acc = gate = sig(zn @ w_g^T + b_g) =================
#pragma unroll
    for (int e = 0; e < 32; e++) acc[e] = 0.f;
    mm2(acc, ZH, WH, ao0, ao1, bo0, bo1);
    __syncthreads();
    prefetch_half(WH, g_w[5][0], t);
    CP_WAIT1();
    __syncthreads();
    mm2(acc, ZH, WL, ao0, ao1, bo0, bo1);
    __syncthreads();                         // WL free; all zn reads done
    prefetch_half(WL, g_w[5][1], t);
#pragma unroll
    for (int i = 0; i < 4; i++) {
#pragma unroll
        for (int nb = 0; nb < 4; nb++) {
            int e = ((i >> 1) * 4 + nb) * 4 + (i & 1) * 2;
            int col = wc + nb * 8 + qt * 2;
            acc[e]   = sigm(acc[e]   + sb[512 + col]);
            acc[e+1] = sigm(acc[e+1] + sb[512 + col+1]);
        }
    }
    // LN_out stats from red (written stage 3, visible since then)
    {
        float mu4[4], rs4[4];
#pragma unroll
        for (int i = 0; i < 4; i++) {
            int row = wr + ((i >> 1) << 4) + ((i & 1) << 3) + quad;
            float s = 0.f, s2 = 0.f;
#pragma unroll
            for (int k = 0; k < 4; k++) { float2 p = red[row * 4 + k]; s += p.x; s2 += p.y; }
            mu4[i] = s * (1.f / 128);
            rs4[i] = rsqrtf(fmaxf(s2 * (1.f / 128) - mu4[i] * mu4[i], 0.f) + 1e-5f);
        }
        // overwrite zn smem with xn hi; write xn lo to XL (stage-5 3rd pass)
#pragma unroll
        for (int i = 0; i < 4; i++) {
            int row = wr + ((i >> 1) << 4) + ((i & 1) << 3) + quad;
#pragma unroll
            for (int nb = 0; nb < 4; nb++) {
                int e = ((i >> 1) * 4 + nb) * 4 + (i & 1) * 2;
                int col = wc + nb * 8 + qt * 2;
                float v0 = (xr[e]   - mu4[i]) * rs4[i] * sb[768 + col]   + sb[896 + col];
                float v1 = (xr[e+1] - mu4[i]) * rs4[i] * sb[768 + col+1] + sb[896 + col+1];
                __half h0 = __float2half(v0);
                __half h1 = __float2half(v1);
                __half l0 = __float2half(v0 - __half2float(h0));
                __half l1 = __float2half(v1 - __half2float(h1));
                uint32_t hh = ((uint32_t)__half_as_ushort(h1) << 16) | __half_as_ushort(h0);
                uint32_t ll = ((uint32_t)__half_as_ushort(l1) << 16) | __half_as_ushort(l0);
                uint32_t off = (uint32_t)row * STR + (uint32_t)col * 2u;
                *(uint32_t*)(sm + off) = hh;
                *(uint32_t*)(sm + OFF_XL + off) = ll;
            }
        }
    }
    CP_WAIT1();                              // Wh(5) done; Wl(5) in flight
    __syncthreads();                         // xn visible CTA-wide

    // ====== stage 5: out = (xn @ w_z^T + b_z) * gate  (3 passes) ======
#pragma unroll
    for (int e = 0; e < 32; e++) xr[e] = 0.f;
    mm2(xr, ZH, WH, ao0, ao1, bo0, bo1);     // Ah*Bh
    mm2(xr, XL, WH, ao0, ao1, bo0, bo1);     // Al*Bh (xn-lo correction)
    CP_WAIT0();                              // Wl(5) done (per-thread)
    __syncthreads();                         // ... and visible CTA-wide
    mm2(xr, ZH, WL, ao0, ao1, bo0, bo1);     // Ah*Bl
#pragma unroll
    for (int i = 0; i < 4; i++) {
        int row = wr + ((i >> 1) << 4) + ((i & 1) << 3) + quad;
        float* orow = out + (row0 + row) * 128;
#pragma unroll
        for (int nb = 0; nb < 4; nb++) {
            int e = ((i >> 1) * 4 + nb) * 4 + (i & 1) * 2;
            int col = wc + nb * 8 + qt * 2;
            float2 o;
            o.x = (xr[e]   + sb[640 + col])   * acc[e];
            o.y = (xr[e+1] + sb[640 + col+1]) * acc[e+1];
            *(float2*)(orow + col) = o;
        }
    }
}

extern "C" void kernel_launch(void* const* d_in, const int* in_sizes, int n_in,
                              void* d_out, int out_size) {
    const float* z        = (const float*)d_in[0];
    const float* mask     = (const float*)d_in[1];
    const float* w_ap     = (const float*)d_in[2];
    const float* b_ap     = (const float*)d_in[3];
    const float* w_bp     = (const float*)d_in[4];
    const float* b_bp     = (const float*)d_in[5];
    const float* w_ag     = (const float*)d_in[6];
    const float* b_ag     = (const float*)d_in[7];
    const float* w_bg     = (const float*)d_in[8];
    const float* b_bg     = (const float*)d_in[9];
    const float* w_g      = (const float*)d_in[10];
    const float* b_g      = (const float*)d_in[11];
    const float* w_z      = (const float*)d_in[12];
    const float* b_z      = (const float*)d_in[13];
    const float* ln_in_w  = (const float*)d_in[14];
    const float* ln_in_b  = (const float*)d_in[15];
    const float* ln_out_w = (const float*)d_in[16];
    const float* ln_out_b = (const float*)d_in[17];
    float* out = (float*)d_out;

    const int rows = in_sizes[1];      // B*N*N
    const int nblocks = rows / 64;     // 2304

    static int configured = 0;
    if (!configured) {
        cudaFuncSetAttribute(tmu_kernel, cudaFuncAttributeMaxDynamicSharedMemorySize, SMEM_BYTES);
        configured = 1;
    }

    // stage order in g_w: 0=w_ap 1=w_ag 2=w_bp 3=w_bg 4=w_g 5=w_z
    kPrep<<<6, 512>>>(w_ap, w_ag, w_bp, w_bg, w_g, w_z);
    tmu_kernel<<<nblocks, NT, SMEM_BYTES>>>(z, mask,
                                            b_ap, b_ag, b_bp, b_bg, b_g, b_z,
                                            ln_in_w, ln_in_b, ln_out_w, ln_out_b,
                                            out);
}

// round 8
// speedup vs baseline: 2.6862x; 1.1151x over previous
#include <cuda_runtime.h>
#include <cuda_fp16.h>
#include <stdint.h>

// TriangleMultiplicativeUpdate, fused, mma.sync m16n8k16 fp16, 2-term hi/lo
// split (fp32 accum). Round 7: dual-pass fusion (A fragments loaded once per
// k-step feed both Bh and Bl MMAs: 6 LDSM per 16 MMA), stage-5 xn-lo pass
// dropped, final gate (w_g) single-pass hi-only. 12 barriers/round instead
// of 24; 35% less ldmatrix traffic; 15% fewer MMAs.

#define NT 256
#define STR 272u   // smem row stride in bytes (136 fp16): conflict-free ldmatrix

#define OFF_ZH  0u            // zn/xn hi: 64 x 272
#define OFF_WH  17408u        // weight hi: 128 x 272
#define OFF_WL  52224u        // weight lo
#define OFF_SB  87040u        // 8 x 128 floats (biases, ln_out w/b)
#define OFF_MK  91136u        // 64 floats (mask)
#define OFF_RED 91392u        // 64 x 4 float2 (LN_out partials)
#define SMEM_BYTES 93440

// weights as fp16 hi/lo, linear [n][k]; 0=w_ap 1=w_ag 2=w_bp 3=w_bg 4=w_g 5=w_z
__device__ __align__(16) __half g_w[6][2][128 * 128];

__device__ __forceinline__ uint32_t s2u(const void* p) {
    uint32_t a;
    asm("{ .reg .u64 t; cvta.to.shared.u64 t, %1; cvt.u32.u64 %0, t; }" : "=r"(a) : "l"(p));
    return a;
}

#define LDSM4(r, a) \
    asm volatile("ldmatrix.sync.aligned.m8n8.x4.shared.b16 {%0,%1,%2,%3}, [%4];" \
        : "=r"((r)[0]), "=r"((r)[1]), "=r"((r)[2]), "=r"((r)[3]) : "r"(a))

#define MMAOP(d, a, b0, b1) \
    asm volatile("mma.sync.aligned.m16n8k16.row.col.f32.f16.f16.f32 " \
        "{%0,%1,%2,%3}, {%4,%5,%6,%7}, {%8,%9}, {%0,%1,%2,%3};" \
        : "+f"((d)[0]), "+f"((d)[1]), "+f"((d)[2]), "+f"((d)[3]) \
        : "r"((a)[0]), "r"((a)[1]), "r"((a)[2]), "r"((a)[3]), "r"(b0), "r"(b1))

#define CPA16(dst, src) \
    asm volatile("cp.async.cg.shared.global [%0], [%1], 16;" :: "r"(dst), "l"(src))
#define CP_COMMIT() asm volatile("cp.async.commit_group;" ::: "memory")
#define CP_WAIT0()  asm volatile("cp.async.wait_group 0;" ::: "memory")

__device__ __forceinline__ float sigm(float x) { return 1.0f / (1.0f + __expf(-x)); }

// dual pass: acc += A@(Wh^T) + A@(Wl^T); A fragments loaded once per k-step.
__device__ __forceinline__ void mm_dual(float* acc, uint32_t atile,
                                        uint32_t wh, uint32_t wl,
                                        uint32_t ao0, uint32_t ao1,
                                        uint32_t bo0, uint32_t bo1) {
#pragma unroll
    for (int k = 0; k < 8; k++) {
        uint32_t ko = (uint32_t)k * 32u;
        uint32_t A0[4], A1[4], Bh0[4], Bh1[4], Bl0[4], Bl1[4];
        LDSM4(A0, atile + ao0 + ko); LDSM4(A1, atile + ao1 + ko);
        LDSM4(Bh0, wh + bo0 + ko);   LDSM4(Bh1, wh + bo1 + ko);
        LDSM4(Bl0, wl + bo0 + ko);   LDSM4(Bl1, wl + bo1 + ko);
        MMAOP(acc + 0,  A0, Bh0[0], Bh0[1]); MMAOP(acc + 4,  A0, Bh0[2], Bh0[3]);
        MMAOP(acc + 8,  A0, Bh1[0], Bh1[1]); MMAOP(acc + 12, A0, Bh1[2], Bh1[3]);
        MMAOP(acc + 16, A1, Bh0[0], Bh0[1]); MMAOP(acc + 20, A1, Bh0[2], Bh0[3]);
        MMAOP(acc + 24, A1, Bh1[0], Bh1[1]); MMAOP(acc + 28, A1, Bh1[2], Bh1[3]);
        MMAOP(acc + 0,  A0, Bl0[0], Bl0[1]); MMAOP(acc + 4,  A0, Bl0[2], Bl0[3]);
        MMAOP(acc + 8,  A0, Bl1[0], Bl1[1]); MMAOP(acc + 12, A0, Bl1[2], Bl1[3]);
        MMAOP(acc + 16, A1, Bl0[0], Bl0[1]); MMAOP(acc + 20, A1, Bl0[2], Bl0[3]);
        MMAOP(acc + 24, A1, Bl1[0], Bl1[1]); MMAOP(acc + 28, A1, Bl1[2], Bl1[3]);
    }
}

// single pass: acc += A@(W^T)
__device__ __forceinline__ void mm1(float* acc, uint32_t atile, uint32_t wslot,
                                    uint32_t ao0, uint32_t ao1,
                                    uint32_t bo0, uint32_t bo1) {
#pragma unroll
    for (int k = 0; k < 8; k++) {
        uint32_t ko = (uint32_t)k * 32u;
        uint32_t A0[4], A1[4], B0[4], B1[4];
        LDSM4(A0, atile + ao0 + ko); LDSM4(A1, atile + ao1 + ko);
        LDSM4(B0, wslot + bo0 + ko); LDSM4(B1, wslot + bo1 + ko);
        MMAOP(acc + 0,  A0, B0[0], B0[1]); MMAOP(acc + 4,  A0, B0[2], B0[3]);
        MMAOP(acc + 8,  A0, B1[0], B1[1]); MMAOP(acc + 12, A0, B1[2], B1[3]);
        MMAOP(acc + 16, A1, B0[0], B0[1]); MMAOP(acc + 20, A1, B0[2], B0[3]);
        MMAOP(acc + 24, A1, B1[0], B1[1]); MMAOP(acc + 28, A1, B1[2], B1[3]);
    }
}

// async-copy one weight matrix half (32KB) into a padded smem slot; one group
__device__ __forceinline__ void prefetch_half(uint32_t dst, const __half* src, int t) {
    const char* s = (const char*)src;
#pragma unroll
    for (int i = 0; i < 8; i++) {
        int cid = t + i * NT;                  // 2048 16B chunks
        uint32_t d = (uint32_t)(cid >> 4) * STR + (uint32_t)(cid & 15) * 16u;
        CPA16(dst + d, s + (size_t)cid * 16);
    }
    CP_COMMIT();
}

__global__ void kPrep(const float* __restrict__ w0, const float* __restrict__ w1,
                      const float* __restrict__ w2, const float* __restrict__ w3,
                      const float* __restrict__ w4, const float* __restrict__ w5) {
    const float* w;
    switch (blockIdx.x) {
        case 0: w = w0; break; case 1: w = w1; break; case 2: w = w2; break;
        case 3: w = w3; break; case 4: w = w4; break; default: w = w5; break;
    }
    __half* h = g_w[blockIdx.x][0];
    __half* l = g_w[blockIdx.x][1];
    for (int i = threadIdx.x; i < 128 * 128; i += blockDim.x) {
        float v = __ldg(w + i);
        __half hh = __float2half(v);
        h[i] = hh;
        l[i] = __float2half(v - __half2float(hh));
    }
}

__global__ void __launch_bounds__(NT, 2)
tmu_kernel(const float* __restrict__ z, const float* __restrict__ mask,
           const float* __restrict__ b_ap, const float* __restrict__ b_ag,
           const float* __restrict__ b_bp, const float* __restrict__ b_bg,
           const float* __restrict__ b_g,  const float* __restrict__ b_z,
           const float* __restrict__ ln_in_w,  const float* __restrict__ ln_in_b,
           const float* __restrict__ ln_out_w, const float* __restrict__ ln_out_b,
           float* __restrict__ out) {
    extern __shared__ char sm[];
    const uint32_t smb = s2u(sm);
    const int t = threadIdx.x;
    const int w = t >> 5, lid = t & 31;
    const int quad = lid >> 2, qt = lid & 3;
    const int wr = (w & 1) * 32, wc = (w >> 1) * 32;
    const int wcid = w >> 1;
    const size_t row0 = (size_t)blockIdx.x * 64;

    float* sb = (float*)(sm + OFF_SB);
    float* mk = (float*)(sm + OFF_MK);
    float2* red = (float2*)(sm + OFF_RED);

    const uint32_t ZH = smb + OFF_ZH;
    const uint32_t WH = smb + OFF_WH, WL = smb + OFF_WL;

    const uint32_t ao0 = (uint32_t)(wr + (lid & 15)) * STR + (uint32_t)(lid >> 4) * 16u;
    const uint32_t ao1 = ao0 + 16u * STR;
    const uint32_t bo0 = (uint32_t)(wc + (lid & 7) + ((lid >> 4) << 3)) * STR +
                         (uint32_t)((lid >> 3) & 1) * 16u;
    const uint32_t bo1 = bo0 + 16u * STR;

    // bootstrap: weight 0 (both halves) streams while LN_in runs
    prefetch_half(WH, g_w[0][0], t);
    prefetch_half(WL, g_w[0][1], t);

    if (t < 128) {
        sb[t] = __ldg(b_ap + t);           sb[128 + t] = __ldg(b_ag + t);
        sb[256 + t] = __ldg(b_bp + t);     sb[384 + t] = __ldg(b_bg + t);
        sb[512 + t] = __ldg(b_g + t);      sb[640 + t] = __ldg(b_z + t);
        sb[768 + t] = __ldg(ln_out_w + t); sb[896 + t] = __ldg(ln_out_b + t);
    }

    // ---- LN_in: 4 threads/row over 64 rows; write zn (fp16 hi only) ----
    {
        const int r = t >> 2, q = t & 3;
        const float* zr = z + (row0 + r) * 128 + q * 32;
        float v[32], s = 0.f, s2 = 0.f;
#pragma unroll
        for (int i = 0; i < 8; i++) {
            float4 f = __ldg((const float4*)(zr + 4 * i));
            v[4*i] = f.x; v[4*i+1] = f.y; v[4*i+2] = f.z; v[4*i+3] = f.w;
            s += f.x + f.y + f.z + f.w;
            s2 += f.x*f.x + f.y*f.y + f.z*f.z + f.w*f.w;
        }
        s  += __shfl_xor_sync(~0u, s, 1);  s  += __shfl_xor_sync(~0u, s, 2);
        s2 += __shfl_xor_sync(~0u, s2, 1); s2 += __shfl_xor_sync(~0u, s2, 2);
        float mu = s * (1.f / 128);
        float rstd = rsqrtf(fmaxf(s2 * (1.f / 128) - mu * mu, 0.f) + 1e-5f);
#pragma unroll
        for (int j = 0; j < 4; j++) {
            union { uint4 u; __half b[8]; } H;
#pragma unroll
            for (int i = 0; i < 8; i++) {
                int c = q * 32 + j * 8 + i;
                float f = (v[j*8+i] - mu) * rstd * __ldg(ln_in_w + c) + __ldg(ln_in_b + c);
                H.b[i] = __float2half(f);
            }
            uint32_t off = (uint32_t)r * STR + (uint32_t)(q * 4 + j) * 16u;
            *(uint4*)(sm + off) = H.u;
        }
        if (q == 0) mk[r] = __ldg(mask + row0 + r);
    }

    float xr[32], acc[32];

    CP_WAIT0();            // W(0) landed
    __syncthreads();       // ... visible; zn visible

    // ================= stage 0 (ap): xr = zn @ w_ap^T =================
#pragma unroll
    for (int e = 0; e < 32; e++) xr[e] = 0.f;
    mm_dual(xr, ZH, WH, WL, ao0, ao1, bo0, bo1);
    __syncthreads();                          // W slots free
    prefetch_half(WH, g_w[1][0], t);
    prefetch_half(WL, g_w[1][1], t);
    CP_WAIT0();
    __syncthreads();

    // ================= stage 1 (ag): acc = zn @ w_ag^T; xr = a =================
#pragma unroll
    for (int e = 0; e < 32; e++) acc[e] = 0.f;
    mm_dual(acc, ZH, WH, WL, ao0, ao1, bo0, bo1);
    __syncthreads();
    prefetch_half(WH, g_w[2][0], t);
    prefetch_half(WL, g_w[2][1], t);
#pragma unroll
    for (int i = 0; i < 4; i++) {
        int row = wr + ((i >> 1) << 4) + ((i & 1) << 3) + quad;
        float m = mk[row];
#pragma unroll
        for (int nb = 0; nb < 4; nb++) {
            int e = ((i >> 1) * 4 + nb) * 4 + (i & 1) * 2;
            int col = wc + nb * 8 + qt * 2;
            xr[e]   = (xr[e]   + sb[col])   * sigm(acc[e]   + sb[128 + col])   * m;
            xr[e+1] = (xr[e+1] + sb[col+1]) * sigm(acc[e+1] + sb[128 + col+1]) * m;
        }
    }
    CP_WAIT0();
    __syncthreads();

    // ================= stage 2 (bp): acc = zn @ w_bp^T; xr *= (P+b)*m =================
#pragma unroll
    for (int e = 0; e < 32; e++) acc[e] = 0.f;
    mm_dual(acc, ZH, WH, WL, ao0, ao1, bo0, bo1);
    __syncthreads();
    prefetch_half(WH, g_w[3][0], t);
    prefetch_half(WL, g_w[3][1], t);
#pragma unroll
    for (int i = 0; i < 4; i++) {
        int row = wr + ((i >> 1) << 4) + ((i & 1) << 3) + quad;
        float m = mk[row];
#pragma unroll
        for (int nb = 0; nb < 4; nb++) {
            int e = ((i >> 1) * 4 + nb) * 4 + (i & 1) * 2;
            int col = wc + nb * 8 + qt * 2;
            xr[e]   *= (acc[e]   + sb[256 + col])   * m;
            xr[e+1] *= (acc[e+1] + sb[256 + col+1]) * m;
        }
    }
    CP_WAIT0();
    __syncthreads();

    // ====== stage 3 (bg): acc = zn @ w_bg^T; x = xr*sig; LN partials ======
#pragma unroll
    for (int e = 0; e < 32; e++) acc[e] = 0.f;
    mm_dual(acc, ZH, WH, WL, ao0, ao1, bo0, bo1);
    __syncthreads();
    prefetch_half(WH, g_w[4][0], t);          // gate is single-pass: hi only
#pragma unroll
    for (int i = 0; i < 4; i++) {
        int row = wr + ((i >> 1) << 4) + ((i & 1) << 3) + quad;
        float s = 0.f, s2 = 0.f;
#pragma unroll
        for (int nb = 0; nb < 4; nb++) {
            int e = ((i >> 1) * 4 + nb) * 4 + (i & 1) * 2;
            int col = wc + nb * 8 + qt * 2;
            xr[e]   *= sigm(acc[e]   + sb[384 + col]);
            xr[e+1] *= sigm(acc[e+1] + sb[384 + col+1]);
            s  += xr[e] + xr[e+1];
            s2 += xr[e] * xr[e] + xr[e+1] * xr[e+1];
        }
        s  += __shfl_xor_sync(~0u, s, 1);  s  += __shfl_xor_sync(~0u, s, 2);
        s2 += __shfl_xor_sync(~0u, s2, 1); s2 += __shfl_xor_sync(~0u, s2, 2);
        if (qt == 0) red[row * 4 + wcid] = make_float2(s, s2);
    }
    CP_WAIT0();
    __syncthreads();

    // ====== stage 4 (g): acc = gate = sig(zn @ w_g^T + b_g), hi-only ======
#pragma unroll
    for (int e = 0; e < 32; e++) acc[e] = 0.f;
    mm1(acc, ZH, WH, ao0, ao1, bo0, bo1);
    __syncthreads();                          // all zn reads + W reads done
    prefetch_half(WH, g_w[5][0], t);
    prefetch_half(WL, g_w[5][1], t);
#pragma unroll
    for (int i = 0; i < 4; i++) {
#pragma unroll
        for (int nb = 0; nb < 4; nb++) {
            int e = ((i >> 1) * 4 + nb) * 4 + (i & 1) * 2;
            int col = wc + nb * 8 + qt * 2;
            acc[e]   = sigm(acc[e]   + sb[512 + col]);
            acc[e+1] = sigm(acc[e+1] + sb[512 + col+1]);
        }
    }
    // LN_out stats (red written stage 3, sync'd since) + xn -> ZH (fp16 hi)
    {
        float mu4[4], rs4[4];
#pragma unroll
        for (int i = 0; i < 4; i++) {
            int row = wr + ((i >> 1) << 4) + ((i & 1) << 3) + quad;
            float s = 0.f, s2 = 0.f;
#pragma unroll
            for (int k = 0; k < 4; k++) { float2 p = red[row * 4 + k]; s += p.x; s2 += p.y; }
            mu4[i] = s * (1.f / 128);
            rs4[i] = rsqrtf(fmaxf(s2 * (1.f / 128) - mu4[i] * mu4[i], 0.f) + 1e-5f);
        }
#pragma unroll
        for (int i = 0; i < 4; i++) {
            int row = wr + ((i >> 1) << 4) + ((i & 1) << 3) + quad;
#pragma unroll
            for (int nb = 0; nb < 4; nb++) {
                int e = ((i >> 1) * 4 + nb) * 4 + (i & 1) * 2;
                int col = wc + nb * 8 + qt * 2;
                float v0 = (xr[e]   - mu4[i]) * rs4[i] * sb[768 + col]   + sb[896 + col];
                float v1 = (xr[e+1] - mu4[i]) * rs4[i] * sb[768 + col+1] + sb[896 + col+1];
                uint32_t hh = ((uint32_t)__half_as_ushort(__float2half(v1)) << 16) |
                              __half_as_ushort(__float2half(v0));
                *(uint32_t*)(sm + (uint32_t)row * STR + (uint32_t)col * 2u) = hh;
            }
        }
    }
    CP_WAIT0();                               // W(5) landed
    __syncthreads();                          // ... and xn visible CTA-wide

    // ====== stage 5 (z): out = (xn @ w_z^T + b_z) * gate ======
#pragma unroll
    for (int e = 0; e < 32; e++) xr[e] = 0.f;
    mm_dual(xr, ZH, WH, WL, ao0, ao1, bo0, bo1);
#pragma unroll
    for (int i = 0; i < 4; i++) {
        int row = wr + ((i >> 1) << 4) + ((i & 1) << 3) + quad;
        float* orow = out + (row0 + row) * 128;
#pragma unroll
        for (int nb = 0; nb < 4; nb++) {
            int e = ((i >> 1) * 4 + nb) * 4 + (i & 1) * 2;
            int col = wc + nb * 8 + qt * 2;
            float2 o;
            o.x = (xr[e]   + sb[640 + col])   * acc[e];
            o.y = (xr[e+1] + sb[640 + col+1]) * acc[e+1];
            *(float2*)(orow + col) = o;
        }
    }
}

extern "C" void kernel_launch(void* const* d_in, const int* in_sizes, int n_in,
                              void* d_out, int out_size) {
    const float* z        = (const float*)d_in[0];
    const float* mask     = (const float*)d_in[1];
    const float* w_ap     = (const float*)d_in[2];
    const float* b_ap     = (const float*)d_in[3];
    const float* w_bp     = (const float*)d_in[4];
    const float* b_bp     = (const float*)d_in[5];
    const float* w_ag     = (const float*)d_in[6];
    const float* b_ag     = (const float*)d_in[7];
    const float* w_bg     = (const float*)d_in[8];
    const float* b_bg     = (const float*)d_in[9];
    const float* w_g      = (const float*)d_in[10];
    const float* b_g      = (const float*)d_in[11];
    const float* w_z      = (const float*)d_in[12];
    const float* b_z      = (const float*)d_in[13];
    const float* ln_in_w  = (const float*)d_in[14];
    const float* ln_in_b  = (const float*)d_in[15];
    const float* ln_out_w = (const float*)d_in[16];
    const float* ln_out_b = (const float*)d_in[17];
    float* out = (float*)d_out;

    const int rows = in_sizes[1];      // B*N*N
    const int nblocks = rows / 64;     // 2304

    static int configured = 0;
    if (!configured) {
        cudaFuncSetAttribute(tmu_kernel, cudaFuncAttributeMaxDynamicSharedMemorySize, SMEM_BYTES);
        configured = 1;
    }

    // stage order in g_w: 0=w_ap 1=w_ag 2=w_bp 3=w_bg 4=w_g 5=w_z
    kPrep<<<6, 512>>>(w_ap, w_ag, w_bp, w_bg, w_g, w_z);
    tmu_kernel<<<nblocks, NT, SMEM_BYTES>>>(z, mask,
                                            b_ap, b_ag, b_bp, b_bg, b_g, b_z,
                                            ln_in_w, ln_in_b, ln_out_w, ln_out_b,
                                            out);
}

// round 9
// speedup vs baseline: 3.2536x; 1.2112x over previous
#include <cuda_runtime.h>
#include <cuda_fp16.h>
#include <stdint.h>

// TriangleMultiplicativeUpdate, fused, mma.sync m16n8k16 fp16 (fp32 accum).
// Round 8: single-pass hi-only weights on ap/ag/bp/bg/g (error chain says
// ~5e-4 total, <1e-3 gate); dual-pass (hi+lo) kept only on w_z. Weight-hi
// matrices ping-pong between two smem slots with cp.async group tracking so
// copies hide under the previous stage's MMAs.

#define NT 256
#define STR 272u   // smem row stride in bytes (136 fp16): conflict-free ldmatrix

#define OFF_ZH  0u            // zn/xn hi: 64 x 272
#define OFF_WA  17408u        // weight slot A: 128 x 272
#define OFF_WB  52224u        // weight slot B
#define OFF_SB  87040u        // 8 x 128 floats (biases, ln_out w/b)
#define OFF_MK  91136u        // 64 floats (mask)
#define OFF_RED 91392u        // 64 x 4 float2 (LN_out partials)
#define SMEM_BYTES 93440

// weights as fp16 hi/lo, linear [n][k]; 0=w_ap 1=w_ag 2=w_bp 3=w_bg 4=w_g 5=w_z
__device__ __align__(16) __half g_w[6][2][128 * 128];

__device__ __forceinline__ uint32_t s2u(const void* p) {
    uint32_t a;
    asm("{ .reg .u64 t; cvta.to.shared.u64 t, %1; cvt.u32.u64 %0, t; }" : "=r"(a) : "l"(p));
    return a;
}

#define LDSM4(r, a) \
    asm volatile("ldmatrix.sync.aligned.m8n8.x4.shared.b16 {%0,%1,%2,%3}, [%4];" \
        : "=r"((r)[0]), "=r"((r)[1]), "=r"((r)[2]), "=r"((r)[3]) : "r"(a))

#define MMAOP(d, a, b0, b1) \
    asm volatile("mma.sync.aligned.m16n8k16.row.col.f32.f16.f16.f32 " \
        "{%0,%1,%2,%3}, {%4,%5,%6,%7}, {%8,%9}, {%0,%1,%2,%3};" \
        : "+f"((d)[0]), "+f"((d)[1]), "+f"((d)[2]), "+f"((d)[3]) \
        : "r"((a)[0]), "r"((a)[1]), "r"((a)[2]), "r"((a)[3]), "r"(b0), "r"(b1))

#define CPA16(dst, src) \
    asm volatile("cp.async.cg.shared.global [%0], [%1], 16;" :: "r"(dst), "l"(src))
#define CP_COMMIT() asm volatile("cp.async.commit_group;" ::: "memory")
#define CP_WAIT0()  asm volatile("cp.async.wait_group 0;" ::: "memory")
#define CP_WAIT1()  asm volatile("cp.async.wait_group 1;" ::: "memory")

__device__ __forceinline__ float sigm(float x) { return 1.0f / (1.0f + __expf(-x)); }

// single pass: acc += A@(W^T)
__device__ __forceinline__ void mm1(float* acc, uint32_t atile, uint32_t wslot,
                                    uint32_t ao0, uint32_t ao1,
                                    uint32_t bo0, uint32_t bo1) {
#pragma unroll
    for (int k = 0; k < 8; k++) {
        uint32_t ko = (uint32_t)k * 32u;
        uint32_t A0[4], A1[4], B0[4], B1[4];
        LDSM4(A0, atile + ao0 + ko); LDSM4(A1, atile + ao1 + ko);
        LDSM4(B0, wslot + bo0 + ko); LDSM4(B1, wslot + bo1 + ko);
        MMAOP(acc + 0,  A0, B0[0], B0[1]); MMAOP(acc + 4,  A0, B0[2], B0[3]);
        MMAOP(acc + 8,  A0, B1[0], B1[1]); MMAOP(acc + 12, A0, B1[2], B1[3]);
        MMAOP(acc + 16, A1, B0[0], B0[1]); MMAOP(acc + 20, A1, B0[2], B0[3]);
        MMAOP(acc + 24, A1, B1[0], B1[1]); MMAOP(acc + 28, A1, B1[2], B1[3]);
    }
}

// dual pass: acc += A@(Wh^T) + A@(Wl^T); A fragments loaded once per k-step.
__device__ __forceinline__ void mm_dual(float* acc, uint32_t atile,
                                        uint32_t wh, uint32_t wl,
                                        uint32_t ao0, uint32_t ao1,
                                        uint32_t bo0, uint32_t bo1) {
#pragma unroll
    for (int k = 0; k < 8; k++) {
        uint32_t ko = (uint32_t)k * 32u;
        uint32_t A0[4], A1[4], Bh0[4], Bh1[4], Bl0[4], Bl1[4];
        LDSM4(A0, atile + ao0 + ko); LDSM4(A1, atile + ao1 + ko);
        LDSM4(Bh0, wh + bo0 + ko);   LDSM4(Bh1, wh + bo1 + ko);
        LDSM4(Bl0, wl + bo0 + ko);   LDSM4(Bl1, wl + bo1 + ko);
        MMAOP(acc + 0,  A0, Bh0[0], Bh0[1]); MMAOP(acc + 4,  A0, Bh0[2], Bh0[3]);
        MMAOP(acc + 8,  A0, Bh1[0], Bh1[1]); MMAOP(acc + 12, A0, Bh1[2], Bh1[3]);
        MMAOP(acc + 16, A1, Bh0[0], Bh0[1]); MMAOP(acc + 20, A1, Bh0[2], Bh0[3]);
        MMAOP(acc + 24, A1, Bh1[0], Bh1[1]); MMAOP(acc + 28, A1, Bh1[2], Bh1[3]);
        MMAOP(acc + 0,  A0, Bl0[0], Bl0[1]); MMAOP(acc + 4,  A0, Bl0[2], Bl0[3]);
        MMAOP(acc + 8,  A0, Bl1[0], Bl1[1]); MMAOP(acc + 12, A0, Bl1[2], Bl1[3]);
        MMAOP(acc + 16, A1, Bl0[0], Bl0[1]); MMAOP(acc + 20, A1, Bl0[2], Bl0[3]);
        MMAOP(acc + 24, A1, Bl1[0], Bl1[1]); MMAOP(acc + 28, A1, Bl1[2], Bl1[3]);
    }
}

// async-copy one weight matrix half (32KB) into a padded smem slot; one group
__device__ __forceinline__ void prefetch_half(uint32_t dst, const __half* src, int t) {
    const char* s = (const char*)src;
#pragma unroll
    for (int i = 0; i < 8; i++) {
        int cid = t + i * NT;                  // 2048 16B chunks
        uint32_t d = (uint32_t)(cid >> 4) * STR + (uint32_t)(cid & 15) * 16u;
        CPA16(dst + d, s + (size_t)cid * 16);
    }
    CP_COMMIT();
}

__global__ void kPrep(const float* __restrict__ w0, const float* __restrict__ w1,
                      const float* __restrict__ w2, const float* __restrict__ w3,
                      const float* __restrict__ w4, const float* __restrict__ w5) {
    const float* w;
    switch (blockIdx.x) {
        case 0: w = w0; break; case 1: w = w1; break; case 2: w = w2; break;
        case 3: w = w3; break; case 4: w = w4; break; default: w = w5; break;
    }
    __half* h = g_w[blockIdx.x][0];
    __half* l = g_w[blockIdx.x][1];
    for (int i = threadIdx.x; i < 128 * 128; i += blockDim.x) {
        float v = __ldg(w + i);
        __half hh = __float2half(v);
        h[i] = hh;
        l[i] = __float2half(v - __half2float(hh));
    }
}

__global__ void __launch_bounds__(NT, 2)
tmu_kernel(const float* __restrict__ z, const float* __restrict__ mask,
           const float* __restrict__ b_ap, const float* __restrict__ b_ag,
           const float* __restrict__ b_bp, const float* __restrict__ b_bg,
           const float* __restrict__ b_g,  const float* __restrict__ b_z,
           const float* __restrict__ ln_in_w,  const float* __restrict__ ln_in_b,
           const float* __restrict__ ln_out_w, const float* __restrict__ ln_out_b,
           float* __restrict__ out) {
    extern __shared__ char sm[];
    const uint32_t smb = s2u(sm);
    const int t = threadIdx.x;
    const int w = t >> 5, lid = t & 31;
    const int quad = lid >> 2, qt = lid & 3;
    const int wr = (w & 1) * 32, wc = (w >> 1) * 32;
    const int wcid = w >> 1;
    const size_t row0 = (size_t)blockIdx.x * 64;

    float* sb = (float*)(sm + OFF_SB);
    float* mk = (float*)(sm + OFF_MK);
    float2* red = (float2*)(sm + OFF_RED);

    const uint32_t ZH = smb + OFF_ZH;
    const uint32_t WA = smb + OFF_WA, WB = smb + OFF_WB;

    const uint32_t ao0 = (uint32_t)(wr + (lid & 15)) * STR + (uint32_t)(lid >> 4) * 16u;
    const uint32_t ao1 = ao0 + 16u * STR;
    const uint32_t bo0 = (uint32_t)(wc + (lid & 7) + ((lid >> 4) << 3)) * STR +
                         (uint32_t)((lid >> 3) & 1) * 16u;
    const uint32_t bo1 = bo0 + 16u * STR;

    // bootstrap: w0->A, w1->B stream while LN_in runs (2 groups in flight)
    prefetch_half(WA, g_w[0][0], t);
    prefetch_half(WB, g_w[1][0], t);

    if (t < 128) {
        sb[t] = __ldg(b_ap + t);           sb[128 + t] = __ldg(b_ag + t);
        sb[256 + t] = __ldg(b_bp + t);     sb[384 + t] = __ldg(b_bg + t);
        sb[512 + t] = __ldg(b_g + t);      sb[640 + t] = __ldg(b_z + t);
        sb[768 + t] = __ldg(ln_out_w + t); sb[896 + t] = __ldg(ln_out_b + t);
    }

    // ---- LN_in: 4 threads/row over 64 rows; write zn (fp16 hi only) ----
    {
        const int r = t >> 2, q = t & 3;
        const float* zr = z + (row0 + r) * 128 + q * 32;
        float v[32], s = 0.f, s2 = 0.f;
#pragma unroll
        for (int i = 0; i < 8; i++) {
            float4 f = __ldg((const float4*)(zr + 4 * i));
            v[4*i] = f.x; v[4*i+1] = f.y; v[4*i+2] = f.z; v[4*i+3] = f.w;
            s += f.x + f.y + f.z + f.w;
            s2 += f.x*f.x + f.y*f.y + f.z*f.z + f.w*f.w;
        }
        s  += __shfl_xor_sync(~0u, s, 1);  s  += __shfl_xor_sync(~0u, s, 2);
        s2 += __shfl_xor_sync(~0u, s2, 1); s2 += __shfl_xor_sync(~0u, s2, 2);
        float mu = s * (1.f / 128);
        float rstd = rsqrtf(fmaxf(s2 * (1.f / 128) - mu * mu, 0.f) + 1e-5f);
#pragma unroll
        for (int j = 0; j < 4; j++) {
            union { uint4 u; __half b[8]; } H;
#pragma unroll
            for (int i = 0; i < 8; i++) {
                int c = q * 32 + j * 8 + i;
                float f = (v[j*8+i] - mu) * rstd * __ldg(ln_in_w + c) + __ldg(ln_in_b + c);
                H.b[i] = __float2half(f);
            }
            uint32_t off = (uint32_t)r * STR + (uint32_t)(q * 4 + j) * 16u;
            *(uint4*)(sm + off) = H.u;
        }
        if (q == 0) mk[r] = __ldg(mask + row0 + r);
    }

    float xr[32], acc[32];

    CP_WAIT1();            // w0 landed (w1 may still be in flight)
    __syncthreads();       // w0 + zn visible

    // ================= stage 0 (ap, slot A): xr = zn @ w_ap^T =================
#pragma unroll
    for (int e = 0; e < 32; e++) xr[e] = 0.f;
    mm1(xr, ZH, WA, ao0, ao1, bo0, bo1);
    __syncthreads();                          // slot A free
    prefetch_half(WA, g_w[2][0], t);          // w2 -> A (overlaps stage 1)
    CP_WAIT1();                               // w1 landed
    __syncthreads();

    // ============ stage 1 (ag, slot B): acc = zn @ w_ag^T; xr = a ============
#pragma unroll
    for (int e = 0; e < 32; e++) acc[e] = 0.f;
    mm1(acc, ZH, WB, ao0, ao1, bo0, bo1);
    __syncthreads();                          // slot B free
    prefetch_half(WB, g_w[3][0], t);          // w3 -> B
#pragma unroll
    for (int i = 0; i < 4; i++) {
        int row = wr + ((i >> 1) << 4) + ((i & 1) << 3) + quad;
        float m = mk[row];
#pragma unroll
        for (int nb = 0; nb < 4; nb++) {
            int e = ((i >> 1) * 4 + nb) * 4 + (i & 1) * 2;
            int col = wc + nb * 8 + qt * 2;
            xr[e]   = (xr[e]   + sb[col])   * sigm(acc[e]   + sb[128 + col])   * m;
            xr[e+1] = (xr[e+1] + sb[col+1]) * sigm(acc[e+1] + sb[128 + col+1]) * m;
        }
    }
    CP_WAIT1();                               // w2 landed
    __syncthreads();

    // ========= stage 2 (bp, slot A): acc = zn @ w_bp^T; xr *= (P+b)*m =========
#pragma unroll
    for (int e = 0; e < 32; e++) acc[e] = 0.f;
    mm1(acc, ZH, WA, ao0, ao1, bo0, bo1);
    __syncthreads();
    prefetch_half(WA, g_w[4][0], t);          // w4 -> A
#pragma unroll
    for (int i = 0; i < 4; i++) {
        int row = wr + ((i >> 1) << 4) + ((i & 1) << 3) + quad;
        float m = mk[row];
#pragma unroll
        for (int nb = 0; nb < 4; nb++) {
            int e = ((i >> 1) * 4 + nb) * 4 + (i & 1) * 2;
            int col = wc + nb * 8 + qt * 2;
            xr[e]   *= (acc[e]   + sb[256 + col])   * m;
            xr[e+1] *= (acc[e+1] + sb[256 + col+1]) * m;
        }
    }
    CP_WAIT1();                               // w3 landed
    __syncthreads();

    // ==== stage 3 (bg, slot B): acc = zn @ w_bg^T; x = xr*sig; LN partials ====
#pragma unroll
    for (int e = 0; e < 32; e++) acc[e] = 0.f;
    mm1(acc, ZH, WB, ao0, ao1, bo0, bo1);
    __syncthreads();
    prefetch_half(WB, g_w[5][0], t);          // w5 hi -> B
#pragma unroll
    for (int i = 0; i < 4; i++) {
        int row = wr + ((i >> 1) << 4) + ((i & 1) << 3) + quad;
        float s = 0.f, s2 = 0.f;
#pragma unroll
        for (int nb = 0; nb < 4; nb++) {
            int e = ((i >> 1) * 4 + nb) * 4 + (i & 1) * 2;
            int col = wc + nb * 8 + qt * 2;
            xr[e]   *= sigm(acc[e]   + sb[384 + col]);
            xr[e+1] *= sigm(acc[e+1] + sb[384 + col+1]);
            s  += xr[e] + xr[e+1];
            s2 += xr[e] * xr[e] + xr[e+1] * xr[e+1];
        }
        s  += __shfl_xor_sync(~0u, s, 1);  s  += __shfl_xor_sync(~0u, s, 2);
        s2 += __shfl_xor_sync(~0u, s2, 1); s2 += __shfl_xor_sync(~0u, s2, 2);
        if (qt == 0) red[row * 4 + wcid] = make_float2(s, s2);
    }
    CP_WAIT1();                               // w4 landed
    __syncthreads();

    // ====== stage 4 (g, slot A): acc = gate = sig(zn @ w_g^T + b_g) ======
#pragma unroll
    for (int e = 0; e < 32; e++) acc[e] = 0.f;
    mm1(acc, ZH, WA, ao0, ao1, bo0, bo1);
    __syncthreads();                          // slot A free; all zn reads done
    prefetch_half(WA, g_w[5][1], t);          // w5 lo -> A
#pragma unroll
    for (int i = 0; i < 4; i++) {
#pragma unroll
        for (int nb = 0; nb < 4; nb++) {
            int e = ((i >> 1) * 4 + nb) * 4 + (i & 1) * 2;
            int col = wc + nb * 8 + qt * 2;
            acc[e]   = sigm(acc[e]   + sb[512 + col]);
            acc[e+1] = sigm(acc[e+1] + sb[512 + col+1]);
        }
    }
    // LN_out stats (red written stage 3, sync'd since) + xn -> ZH (fp16 hi)
    {
        float mu4[4], rs4[4];
#pragma unroll
        for (int i = 0; i < 4; i++) {
            int row = wr + ((i >> 1) << 4) + ((i & 1) << 3) + quad;
            float s = 0.f, s2 = 0.f;
#pragma unroll
            for (int k = 0; k < 4; k++) { float2 p = red[row * 4 + k]; s += p.x; s2 += p.y; }
            mu4[i] = s * (1.f / 128);
            rs4[i] = rsqrtf(fmaxf(s2 * (1.f / 128) - mu4[i] * mu4[i], 0.f) + 1e-5f);
        }
#pragma unroll
        for (int i = 0; i < 4; i++) {
            int row = wr + ((i >> 1) << 4) + ((i & 1) << 3) + quad;
#pragma unroll
            for (int nb = 0; nb < 4; nb++) {
                int e = ((i >> 1) * 4 + nb) * 4 + (i & 1) * 2;
                int col = wc + nb * 8 + qt * 2;
                float v0 = (xr[e]   - mu4[i]) * rs4[i] * sb[768 + col]   + sb[896 + col];
                float v1 = (xr[e+1] - mu4[i]) * rs4[i] * sb[768 + col+1] + sb[896 + col+1];
                uint32_t hh = ((uint32_t)__half_as_ushort(__float2half(v1)) << 16) |
                              __half_as_ushort(__float2half(v0));
                *(uint32_t*)(sm + (uint32_t)row * STR + (uint32_t)col * 2u) = hh;
            }
        }
    }
    CP_WAIT0();                               // w5 hi + lo landed (per-thread)
    __syncthreads();                          // ... and xn + w5 visible CTA-wide

    // == stage 5 (z, dual: hi in B, lo in A): out = (xn @ w_z^T + b_z) * gate ==
#pragma unroll
    for (int e = 0; e < 32; e++) xr[e] = 0.f;
    mm_dual(xr, ZH, WB, WA, ao0, ao1, bo0, bo1);
#pragma unroll
    for (int i = 0; i < 4; i++) {
        int row = wr + ((i >> 1) << 4) + ((i & 1) << 3) + quad;
        float* orow = out + (row0 + row) * 128;
#pragma unroll
        for (int nb = 0; nb < 4; nb++) {
            int e = ((i >> 1) * 4 + nb) * 4 + (i & 1) * 2;
            int col = wc + nb * 8 + qt * 2;
            float2 o;
            o.x = (xr[e]   + sb[640 + col])   * acc[e];
            o.y = (xr[e+1] + sb[640 + col+1]) * acc[e+1];
            *(float2*)(orow + col) = o;
        }
    }
}

extern "C" void kernel_launch(void* const* d_in, const int* in_sizes, int n_in,
                              void* d_out, int out_size) {
    const float* z        = (const float*)d_in[0];
    const float* mask     = (const float*)d_in[1];
    const float* w_ap     = (const float*)d_in[2];
    const float* b_ap     = (const float*)d_in[3];
    const float* w_bp     = (const float*)d_in[4];
    const float* b_bp     = (const float*)d_in[5];
    const float* w_ag     = (const float*)d_in[6];
    const float* b_ag     = (const float*)d_in[7];
    const float* w_bg     = (const float*)d_in[8];
    const float* b_bg     = (const float*)d_in[9];
    const float* w_g      = (const float*)d_in[10];
    const float* b_g      = (const float*)d_in[11];
    const float* w_z      = (const float*)d_in[12];
    const float* b_z      = (const float*)d_in[13];
    const float* ln_in_w  = (const float*)d_in[14];
    const float* ln_in_b  = (const float*)d_in[15];
    const float* ln_out_w = (const float*)d_in[16];
    const float* ln_out_b = (const float*)d_in[17];
    float* out = (float*)d_out;

    const int rows = in_sizes[1];      // B*N*N
    const int nblocks = rows / 64;     // 2304

    static int configured = 0;
    if (!configured) {
        cudaFuncSetAttribute(tmu_kernel, cudaFuncAttributeMaxDynamicSharedMemorySize, SMEM_BYTES);
        configured = 1;
    }

    // stage order in g_w: 0=w_ap 1=w_ag 2=w_bp 3=w_bg 4=w_g 5=w_z
    kPrep<<<6, 512>>>(w_ap, w_ag, w_bp, w_bg, w_g, w_z);
    tmu_kernel<<<nblocks, NT, SMEM_BYTES>>>(z, mask,
                                            b_ap, b_ag, b_bp, b_bg, b_g, b_z,
                                            ln_in_w, ln_in_b, ln_out_w, ln_out_b,
                                            out);
}

// round 10
// speedup vs baseline: 3.4751x; 1.0681x over previous
#include <cuda_runtime.h>
#include <cuda_fp16.h>
#include <stdint.h>

// TriangleMultiplicativeUpdate, fused, mma.sync m16n8k16 fp16 (fp32 accum),
// all matmuls single-pass fp16-hi weights (error chain: ~5.5e-4 < 1e-3).
// Round 9: stage pairs (ap,ag) and (bp,bg) fused into single passes that
// load A fragments once and feed two accumulators (6 LDSM per 16 MMA);
// the 'a' tensor spills to smem fp16 between pairs to fit the register file.
// 8 barriers/tile, 160 LDSM.x4/warp, 384 MMA/warp.

#define NT 256
#define STR 272u   // smem row stride in bytes (136 fp16): conflict-free ldmatrix

#define OFF_ZH  0u            // zn/xn hi: 64 x 272
#define OFF_AH  17408u        // 'a' spill: 64 x 272 fp16
#define OFF_WA  34816u        // weight slot A: 128 x 272
#define OFF_WB  69632u        // weight slot B
#define OFF_SB  104448u       // 8 x 128 floats (biases, ln_out w/b)
#define OFF_MK  108544u       // 64 floats (mask)
#define OFF_RED 108800u       // 64 x 4 float2 (LN_out partials)
#define SMEM_BYTES 110848

// weights as fp16 (hi only), linear [n][k]; 0=w_ap 1=w_ag 2=w_bp 3=w_bg 4=w_g 5=w_z
__device__ __align__(16) __half g_w[6][128 * 128];

__device__ __forceinline__ uint32_t s2u(const void* p) {
    uint32_t a;
    asm("{ .reg .u64 t; cvta.to.shared.u64 t, %1; cvt.u32.u64 %0, t; }" : "=r"(a) : "l"(p));
    return a;
}

#define LDSM4(r, a) \
    asm volatile("ldmatrix.sync.aligned.m8n8.x4.shared.b16 {%0,%1,%2,%3}, [%4];" \
        : "=r"((r)[0]), "=r"((r)[1]), "=r"((r)[2]), "=r"((r)[3]) : "r"(a))

#define MMAOP(d, a, b0, b1) \
    asm volatile("mma.sync.aligned.m16n8k16.row.col.f32.f16.f16.f32 " \
        "{%0,%1,%2,%3}, {%4,%5,%6,%7}, {%8,%9}, {%0,%1,%2,%3};" \
        : "+f"((d)[0]), "+f"((d)[1]), "+f"((d)[2]), "+f"((d)[3]) \
        : "r"((a)[0]), "r"((a)[1]), "r"((a)[2]), "r"((a)[3]), "r"(b0), "r"(b1))

#define CPA16(dst, src) \
    asm volatile("cp.async.cg.shared.global [%0], [%1], 16;" :: "r"(dst), "l"(src))
#define CP_COMMIT() asm volatile("cp.async.commit_group;" ::: "memory")
#define CP_WAIT0()  asm volatile("cp.async.wait_group 0;" ::: "memory")

__device__ __forceinline__ float sigm(float x) { return 1.0f / (1.0f + __expf(-x)); }

// single pass: acc += A@(W^T)
__device__ __forceinline__ void mm1(float* acc, uint32_t atile, uint32_t wslot,
                                    uint32_t ao0, uint32_t ao1,
                                    uint32_t bo0, uint32_t bo1) {
#pragma unroll
    for (int k = 0; k < 8; k++) {
        uint32_t ko = (uint32_t)k * 32u;
        uint32_t A0[4], A1[4], B0[4], B1[4];
        LDSM4(A0, atile + ao0 + ko); LDSM4(A1, atile + ao1 + ko);
        LDSM4(B0, wslot + bo0 + ko); LDSM4(B1, wslot + bo1 + ko);
        MMAOP(acc + 0,  A0, B0[0], B0[1]); MMAOP(acc + 4,  A0, B0[2], B0[3]);
        MMAOP(acc + 8,  A0, B1[0], B1[1]); MMAOP(acc + 12, A0, B1[2], B1[3]);
        MMAOP(acc + 16, A1, B0[0], B0[1]); MMAOP(acc + 20, A1, B0[2], B0[3]);
        MMAOP(acc + 24, A1, B1[0], B1[1]); MMAOP(acc + 28, A1, B1[2], B1[3]);
    }
}

// paired pass: accP += A@(Wp^T), accG += A@(Wg^T); A loaded once per k-step.
__device__ __forceinline__ void mm_pair(float* accP, float* accG, uint32_t atile,
                                        uint32_t wp, uint32_t wg,
                                        uint32_t ao0, uint32_t ao1,
                                        uint32_t bo0, uint32_t bo1) {
#pragma unroll
    for (int k = 0; k < 8; k++) {
        uint32_t ko = (uint32_t)k * 32u;
        uint32_t A0[4], A1[4], P0[4], P1[4], G0[4], G1[4];
        LDSM4(A0, atile + ao0 + ko); LDSM4(A1, atile + ao1 + ko);
        LDSM4(P0, wp + bo0 + ko);    LDSM4(P1, wp + bo1 + ko);
        LDSM4(G0, wg + bo0 + ko);    LDSM4(G1, wg + bo1 + ko);
        MMAOP(accP + 0,  A0, P0[0], P0[1]); MMAOP(accP + 4,  A0, P0[2], P0[3]);
        MMAOP(accP + 8,  A0, P1[0], P1[1]); MMAOP(accP + 12, A0, P1[2], P1[3]);
        MMAOP(accP + 16, A1, P0[0], P0[1]); MMAOP(accP + 20, A1, P0[2], P0[3]);
        MMAOP(accP + 24, A1, P1[0], P1[1]); MMAOP(accP + 28, A1, P1[2], P1[3]);
        MMAOP(accG + 0,  A0, G0[0], G0[1]); MMAOP(accG + 4,  A0, G0[2], G0[3]);
        MMAOP(accG + 8,  A0, G1[0], G1[1]); MMAOP(accG + 12, A0, G1[2], G1[3]);
        MMAOP(accG + 16, A1, G0[0], G0[1]); MMAOP(accG + 20, A1, G0[2], G0[3]);
        MMAOP(accG + 24, A1, G1[0], G1[1]); MMAOP(accG + 28, A1, G1[2], G1[3]);
    }
}

// async-copy one weight matrix (32KB) into a padded smem slot; one group
__device__ __forceinline__ void prefetch_w(uint32_t dst, const __half* src, int t) {
    const char* s = (const char*)src;
#pragma unroll
    for (int i = 0; i < 8; i++) {
        int cid = t + i * NT;                  // 2048 16B chunks
        uint32_t d = (uint32_t)(cid >> 4) * STR + (uint32_t)(cid & 15) * 16u;
        CPA16(dst + d, s + (size_t)cid * 16);
    }
    CP_COMMIT();
}

__global__ void kPrep(const float* __restrict__ w0, const float* __restrict__ w1,
                      const float* __restrict__ w2, const float* __restrict__ w3,
                      const float* __restrict__ w4, const float* __restrict__ w5) {
    const float* w;
    switch (blockIdx.x) {
        case 0: w = w0; break; case 1: w = w1; break; case 2: w = w2; break;
        case 3: w = w3; break; case 4: w = w4; break; default: w = w5; break;
    }
    __half* h = g_w[blockIdx.x];
    for (int i = threadIdx.x; i < 128 * 128; i += blockDim.x)
        h[i] = __float2half(__ldg(w + i));
}

__global__ void __launch_bounds__(NT, 2)
tmu_kernel(const float* __restrict__ z, const float* __restrict__ mask,
           const float* __restrict__ b_ap, const float* __restrict__ b_ag,
           const float* __restrict__ b_bp, const float* __restrict__ b_bg,
           const float* __restrict__ b_g,  const float* __restrict__ b_z,
           const float* __restrict__ ln_in_w,  const float* __restrict__ ln_in_b,
           const float* __restrict__ ln_out_w, const float* __restrict__ ln_out_b,
           float* __restrict__ out) {
    extern __shared__ char sm[];
    const uint32_t smb = s2u(sm);
    const int t = threadIdx.x;
    const int w = t >> 5, lid = t & 31;
    const int quad = lid >> 2, qt = lid & 3;
    const int wr = (w & 1) * 32, wc = (w >> 1) * 32;
    const int wcid = w >> 1;
    const size_t row0 = (size_t)blockIdx.x * 64;

    float* sb = (float*)(sm + OFF_SB);
    float* mk = (float*)(sm + OFF_MK);
    float2* red = (float2*)(sm + OFF_RED);

    const uint32_t ZH = smb + OFF_ZH;
    const uint32_t WA = smb + OFF_WA, WB = smb + OFF_WB;

    const uint32_t ao0 = (uint32_t)(wr + (lid & 15)) * STR + (uint32_t)(lid >> 4) * 16u;
    const uint32_t ao1 = ao0 + 16u * STR;
    const uint32_t bo0 = (uint32_t)(wc + (lid & 7) + ((lid >> 4) << 3)) * STR +
                         (uint32_t)((lid >> 3) & 1) * 16u;
    const uint32_t bo1 = bo0 + 16u * STR;

    // bootstrap: w_ap->A, w_ag->B stream while LN_in runs
    prefetch_w(WA, g_w[0], t);
    prefetch_w(WB, g_w[1], t);

    if (t < 128) {
        sb[t] = __ldg(b_ap + t);           sb[128 + t] = __ldg(b_ag + t);
        sb[256 + t] = __ldg(b_bp + t);     sb[384 + t] = __ldg(b_bg + t);
        sb[512 + t] = __ldg(b_g + t);      sb[640 + t] = __ldg(b_z + t);
        sb[768 + t] = __ldg(ln_out_w + t); sb[896 + t] = __ldg(ln_out_b + t);
    }

    // ---- LN_in: 4 threads/row over 64 rows; write zn (fp16) ----
    {
        const int r = t >> 2, q = t & 3;
        const float* zr = z + (row0 + r) * 128 + q * 32;
        float v[32], s = 0.f, s2 = 0.f;
#pragma unroll
        for (int i = 0; i < 8; i++) {
            float4 f = __ldg((const float4*)(zr + 4 * i));
            v[4*i] = f.x; v[4*i+1] = f.y; v[4*i+2] = f.z; v[4*i+3] = f.w;
            s += f.x + f.y + f.z + f.w;
            s2 += f.x*f.x + f.y*f.y + f.z*f.z + f.w*f.w;
        }
        s  += __shfl_xor_sync(~0u, s, 1);  s  += __shfl_xor_sync(~0u, s, 2);
        s2 += __shfl_xor_sync(~0u, s2, 1); s2 += __shfl_xor_sync(~0u, s2, 2);
        float mu = s * (1.f / 128);
        float rstd = rsqrtf(fmaxf(s2 * (1.f / 128) - mu * mu, 0.f) + 1e-5f);
#pragma unroll
        for (int j = 0; j < 4; j++) {
            union { uint4 u; __half b[8]; } H;
#pragma unroll
            for (int i = 0; i < 8; i++) {
                int c = q * 32 + j * 8 + i;
                float f = (v[j*8+i] - mu) * rstd * __ldg(ln_in_w + c) + __ldg(ln_in_b + c);
                H.b[i] = __float2half(f);
            }
            uint32_t off = (uint32_t)r * STR + (uint32_t)(q * 4 + j) * 16u;
            *(uint4*)(sm + off) = H.u;
        }
        if (q == 0) mk[r] = __ldg(mask + row0 + r);
    }

    float xr[32], acc[32];

    CP_WAIT0();            // w_ap + w_ag landed
    __syncthreads();       // ... + zn visible

    // ===== pass P01 (fused): xr = zn @ w_ap^T, acc = zn @ w_ag^T =====
#pragma unroll
    for (int e = 0; e < 32; e++) { xr[e] = 0.f; acc[e] = 0.f; }
    mm_pair(xr, acc, ZH, WA, WB, ao0, ao1, bo0, bo1);
    __syncthreads();                          // slots free
    prefetch_w(WA, g_w[2], t);                // w_bp -> A
    prefetch_w(WB, g_w[3], t);                // w_bg -> B
    // epilogue: a = (P+b_ap)*sig(G+b_ag)*m, spill to AH (fp16)
#pragma unroll
    for (int i = 0; i < 4; i++) {
        int row = wr + ((i >> 1) << 4) + ((i & 1) << 3) + quad;
        float m = mk[row];
#pragma unroll
        for (int nb = 0; nb < 4; nb++) {
            int e = ((i >> 1) * 4 + nb) * 4 + (i & 1) * 2;
            int col = wc + nb * 8 + qt * 2;
            float a0 = (xr[e]   + sb[col])   * sigm(acc[e]   + sb[128 + col])   * m;
            float a1 = (xr[e+1] + sb[col+1]) * sigm(acc[e+1] + sb[128 + col+1]) * m;
            uint32_t p = ((uint32_t)__half_as_ushort(__float2half(a1)) << 16) |
                         __half_as_ushort(__float2half(a0));
            *(uint32_t*)(sm + OFF_AH + (uint32_t)row * STR + (uint32_t)col * 2u) = p;
        }
    }
    CP_WAIT0();                               // w_bp + w_bg landed
    __syncthreads();

    // ===== pass P23 (fused): xr = zn @ w_bp^T, acc = zn @ w_bg^T =====
#pragma unroll
    for (int e = 0; e < 32; e++) { xr[e] = 0.f; acc[e] = 0.f; }
    mm_pair(xr, acc, ZH, WA, WB, ao0, ao1, bo0, bo1);
    __syncthreads();                          // slots free
    prefetch_w(WA, g_w[4], t);                // w_g -> A
    prefetch_w(WB, g_w[5], t);                // w_z -> B
    // epilogue: x = a*(P+b_bp)*m*sig(G+b_bg); LN_out partials
#pragma unroll
    for (int i = 0; i < 4; i++) {
        int row = wr + ((i >> 1) << 4) + ((i & 1) << 3) + quad;
        float m = mk[row];
        float s = 0.f, s2 = 0.f;
#pragma unroll
        for (int nb = 0; nb < 4; nb++) {
            int e = ((i >> 1) * 4 + nb) * 4 + (i & 1) * 2;
            int col = wc + nb * 8 + qt * 2;
            uint32_t p = *(const uint32_t*)(sm + OFF_AH + (uint32_t)row * STR + (uint32_t)col * 2u);
            float a0 = __half2float(__ushort_as_half((uint16_t)(p & 0xFFFF)));
            float a1 = __half2float(__ushort_as_half((uint16_t)(p >> 16)));
            xr[e]   = a0 * (xr[e]   + sb[256 + col])   * m * sigm(acc[e]   + sb[384 + col]);
            xr[e+1] = a1 * (xr[e+1] + sb[256 + col+1]) * m * sigm(acc[e+1] + sb[384 + col+1]);
            s  += xr[e] + xr[e+1];
            s2 += xr[e] * xr[e] + xr[e+1] * xr[e+1];
        }
        s  += __shfl_xor_sync(~0u, s, 1);  s  += __shfl_xor_sync(~0u, s, 2);
        s2 += __shfl_xor_sync(~0u, s2, 1); s2 += __shfl_xor_sync(~0u, s2, 2);
        if (qt == 0) red[row * 4 + wcid] = make_float2(s, s2);
    }
    CP_WAIT0();                               // w_g + w_z landed
    __syncthreads();                          // ... + red visible

    // ===== stage g (slot A): acc = zn @ w_g^T =====
#pragma unroll
    for (int e = 0; e < 32; e++) acc[e] = 0.f;
    mm1(acc, ZH, WA, ao0, ao1, bo0, bo1);
    __syncthreads();                          // all zn reads done CTA-wide

    // gate in regs; LN_out stats; xn -> ZH (fp16)
#pragma unroll
    for (int i = 0; i < 4; i++) {
#pragma unroll
        for (int nb = 0; nb < 4; nb++) {
            int e = ((i >> 1) * 4 + nb) * 4 + (i & 1) * 2;
            int col = wc + nb * 8 + qt * 2;
            acc[e]   = sigm(acc[e]   + sb[512 + col]);
            acc[e+1] = sigm(acc[e+1] + sb[512 + col+1]);
        }
    }
    {
        float mu4[4], rs4[4];
#pragma unroll
        for (int i = 0; i < 4; i++) {
            int row = wr + ((i >> 1) << 4) + ((i & 1) << 3) + quad;
            float s = 0.f, s2 = 0.f;
#pragma unroll
            for (int k = 0; k < 4; k++) { float2 p = red[row * 4 + k]; s += p.x; s2 += p.y; }
            mu4[i] = s * (1.f / 128);
            rs4[i] = rsqrtf(fmaxf(s2 * (1.f / 128) - mu4[i] * mu4[i], 0.f) + 1e-5f);
        }
#pragma unroll
        for (int i = 0; i < 4; i++) {
            int row = wr + ((i >> 1) << 4) + ((i & 1) << 3) + quad;
#pragma unroll
            for (int nb = 0; nb < 4; nb++) {
                int e = ((i >> 1) * 4 + nb) * 4 + (i & 1) * 2;
                int col = wc + nb * 8 + qt * 2;
                float v0 = (xr[e]   - mu4[i]) * rs4[i] * sb[768 + col]   + sb[896 + col];
                float v1 = (xr[e+1] - mu4[i]) * rs4[i] * sb[768 + col+1] + sb[896 + col+1];
                uint32_t hh = ((uint32_t)__half_as_ushort(__float2half(v1)) << 16) |
                              __half_as_ushort(__float2half(v0));
                *(uint32_t*)(sm + (uint32_t)row * STR + (uint32_t)col * 2u) = hh;
            }
        }
    }
    __syncthreads();                          // xn visible CTA-wide

    // ===== stage z (slot B): out = (xn @ w_z^T + b_z) * gate =====
#pragma unroll
    for (int e = 0; e < 32; e++) xr[e] = 0.f;
    mm1(xr, ZH, WB, ao0, ao1, bo0, bo1);
#pragma unroll
    for (int i = 0; i < 4; i++) {
        int row = wr + ((i >> 1) << 4) + ((i & 1) << 3) + quad;
        float* orow = out + (row0 + row) * 128;
#pragma unroll
        for (int nb = 0; nb < 4; nb++) {
            int e = ((i >> 1) * 4 + nb) * 4 + (i & 1) * 2;
            int col = wc + nb * 8 + qt * 2;
            float2 o;
            o.x = (xr[e]   + sb[640 + col])   * acc[e];
            o.y = (xr[e+1] + sb[640 + col+1]) * acc[e+1];
            *(float2*)(orow + col) = o;
        }
    }
}

extern "C" void kernel_launch(void* const* d_in, const int* in_sizes, int n_in,
                              void* d_out, int out_size) {
    const float* z        = (const float*)d_in[0];
    const float* mask     = (const float*)d_in[1];
    const float* w_ap     = (const float*)d_in[2];
    const float* b_ap     = (const float*)d_in[3];
    const float* w_bp     = (const float*)d_in[4];
    const float* b_bp     = (const float*)d_in[5];
    const float* w_ag     = (const float*)d_in[6];
    const float* b_ag     = (const float*)d_in[7];
    const float* w_bg     = (const float*)d_in[8];
    const float* b_bg     = (const float*)d_in[9];
    const float* w_g      = (const float*)d_in[10];
    const float* b_g      = (const float*)d_in[11];
    const float* w_z      = (const float*)d_in[12];
    const float* b_z      = (const float*)d_in[13];
    const float* ln_in_w  = (const float*)d_in[14];
    const float* ln_in_b  = (const float*)d_in[15];
    const float* ln_out_w = (const float*)d_in[16];
    const float* ln_out_b = (const float*)d_in[17];
    float* out = (float*)d_out;

    const int rows = in_sizes[1];      // B*N*N
    const int nblocks = rows / 64;     // 2304

    static int configured = 0;
    if (!configured) {
        cudaFuncSetAttribute(tmu_kernel, cudaFuncAttributeMaxDynamicSharedMemorySize, SMEM_BYTES);
        configured = 1;
    }

    // stage order in g_w: 0=w_ap 1=w_ag 2=w_bp 3=w_bg 4=w_g 5=w_z
    kPrep<<<6, 512>>>(w_ap, w_ag, w_bp, w_bg, w_g, w_z);
    tmu_kernel<<<nblocks, NT, SMEM_BYTES>>>(z, mask,
                                            b_ap, b_ag, b_bp, b_bg, b_g, b_z,
                                            ln_in_w, ln_in_b, ln_out_w, ln_out_b,
                                            out);
}